// round 7
// baseline (speedup 1.0000x reference)
#include <cuda_runtime.h>
#include <math.h>

#define NPTS   4096
#define NBATCH 16
#define NSAMP  1024
#define NK     32
#define NROWS  (NBATCH*NSAMP*NK)      /* 524288 */
#define NSAMPT (NBATCH*NSAMP)         /* 16384  */
#define OUT_OFF (NBATCH*NSAMP*3)      /* 49152  */

// ---------------- device scratch (no allocations allowed) ----------------
__device__ float  g_centroids[NBATCH*NSAMP*3];
__device__ float  g_x0[(size_t)NROWS*68];
__device__ float  g_y0[(size_t)NROWS*64];
__device__ float  g_y1[(size_t)NROWS*64];
__device__ float  g_ymax[(size_t)NSAMPT*128];
__device__ float  g_ymin[(size_t)NSAMPT*128];
__device__ double g_sums[512];
__device__ float  g_scale[256];
__device__ float  g_shift[256];

__global__ void zero_stats_kernel() {
    int t = threadIdx.x;
    if (t < 512) g_sums[t] = 0.0;
}

// ---------------- packed f32x2 helpers (exact RN f32 math) ---------------
__device__ __forceinline__ unsigned long long pk_dup(float x) {
    unsigned long long r; unsigned u = __float_as_uint(x);
    asm("mov.b64 %0, {%1, %1};" : "=l"(r) : "r"(u));
    return r;
}
__device__ __forceinline__ void fma2(unsigned long long& d, unsigned long long a,
                                     unsigned long long b) {
    asm("fma.rn.f32x2 %0, %1, %2, %0;" : "+l"(d) : "l"(a), "l"(b));
}
__device__ __forceinline__ void unpk(unsigned long long v, float& lo, float& hi) {
    unsigned a, b;
    asm("mov.b64 {%0, %1}, %2;" : "=r"(a), "=r"(b) : "l"(v));
    lo = __uint_as_float(a); hi = __uint_as_float(b);
}

// ============================ FPS (kept from round 6: -150us) =============
__global__ __launch_bounds__(1024) void fps_kernel(const float* __restrict__ data,
                                                   const int* __restrict__ initf,
                                                   float* __restrict__ out) {
    extern __shared__ float fsm[];
    float* s_px = fsm;
    float* s_py = fsm + NPTS;
    float* s_pz = fsm + 2*NPTS;
    unsigned* s_rd = (unsigned*)(fsm + 3*NPTS);   // 64 (double-buffered)
    unsigned* s_ri = s_rd + 64;

    const int b = blockIdx.x, tid = threadIdx.x;
    const int lane = tid & 31, wid = tid >> 5;
    const float* db = data + (size_t)b * NPTS * 3;

    float px[4], py[4], pz[4], dist[4];
#pragma unroll
    for (int i = 0; i < 4; i++) {
        int n = tid + i * 1024;
        float x = db[n*3+0], y = db[n*3+1], z = db[n*3+2];
        px[i] = x; py[i] = y; pz[i] = z;
        s_px[n] = x; s_py[n] = y; s_pz[n] = z;
        dist[i] = 1e10f;
    }
    int far = __ldg(initf + b);
    __syncthreads();

    for (int s = 0; s < NSAMP; s++) {
        float cx = s_px[far], cy = s_py[far], cz = s_pz[far];
        if (tid == 0) {
            int o = (b*NSAMP + s) * 3;
            out[o] = cx; out[o+1] = cy; out[o+2] = cz;
            g_centroids[o] = cx; g_centroids[o+1] = cy; g_centroids[o+2] = cz;
        }
        unsigned long long best = 0ull;
#pragma unroll
        for (int i = 0; i < 4; i++) {
            float dx = px[i]-cx, dy = py[i]-cy, dz = pz[i]-cz;
            float d = dx*dx + dy*dy + dz*dz;
            dist[i] = fminf(dist[i], d);
            unsigned long long key =
                ((unsigned long long)__float_as_uint(dist[i]) << 32) |
                (unsigned)(4095 - (tid + i*1024));
            best = best > key ? best : key;
        }
        unsigned d32 = (unsigned)(best >> 32);
        unsigned i32 = (unsigned)best;
        unsigned wd = __reduce_max_sync(0xffffffffu, d32);
        unsigned ci = (d32 == wd) ? i32 : 0u;
        unsigned wi = __reduce_max_sync(0xffffffffu, ci);
        int par = (s & 1) * 32;
        if (lane == 0) { s_rd[par + wid] = wd; s_ri[par + wid] = wi; }
        __syncthreads();
        unsigned dv = s_rd[par + lane], iv = s_ri[par + lane];
        unsigned gd = __reduce_max_sync(0xffffffffu, dv);
        unsigned c2 = (dv == gd) ? iv : 0u;
        unsigned gi = __reduce_max_sync(0xffffffffu, c2);
        far = 4095 - (int)gi;
    }
}

// ==================== stage 2+3: top64 -> top32 -> x0 rows ================
struct Stage3 {
    float px[64], py[64], pz[64];
    unsigned long long sk[64];
    float snx[32], sny[32], snz[32], zw[32];
    int   tk[32];
};

__device__ __forceinline__ unsigned ord_f32(float v) {
    unsigned u = __float_as_uint(v);
    return (u & 0x80000000u) ? ~u : (u | 0x80000000u);
}

__device__ __forceinline__ float sqdist_ref(float cx, float cy, float cz, float an2,
                                            float x, float y, float z) {
    float e   = __fmaf_rn(cz, z, __fmaf_rn(cy, y, __fmul_rn(cx, x)));
    float bn2 = __fadd_rn(__fadd_rn(__fmul_rn(x, x), __fmul_rn(y, y)), __fmul_rn(z, z));
    return __fadd_rn(__fadd_rn(__fmul_rn(-2.f, e), an2), bn2);
}

__global__ __launch_bounds__(256) void build_kernel(const float* __restrict__ data,
                                                    const float* __restrict__ feat) {
    extern __shared__ char bsm[];
    unsigned long long* s_keys = (unsigned long long*)bsm;            // 4096 * 8
    unsigned int*       s_hist = (unsigned int*)(bsm + 32768);        // 4096 * 4
    unsigned long long* s_cand = (unsigned long long*)(bsm + 49152);  // 1024 * 8
    int*                s_tot  = (int*)(bsm + 57344);                 // 256 * 4
    int*                s_ctl  = (int*)(bsm + 58368);                 // [0]=T [1]=m

    const int tid = threadIdx.x;
    const int b = blockIdx.x >> 10, s = blockIdx.x & 1023;
    const float* db = data + (size_t)b * NPTS * 3;
    const int co = (b*NSAMP + s) * 3;
    const float cx = g_centroids[co], cy = g_centroids[co+1], cz = g_centroids[co+2];
    const float an2 = __fadd_rn(__fadd_rn(__fmul_rn(cx, cx), __fmul_rn(cy, cy)),
                                __fmul_rn(cz, cz));

    for (int i = tid; i < 4096; i += 256) s_hist[i] = 0u;
    if (tid == 0) s_ctl[1] = 0;
    __syncthreads();

    for (int i = 0; i < 16; i++) {
        int n = tid + i * 256;
        float x = db[n*3], y = db[n*3+1], z = db[n*3+2];
        float v = sqdist_ref(cx, cy, cz, an2, x, y, z);
        unsigned u = ord_f32(v);
        s_keys[n] = ((unsigned long long)u << 32) | (unsigned)(4095 - n);
        atomicAdd(&s_hist[u >> 20], 1u);
    }
    __syncthreads();

    unsigned tot = 0;
    for (int j = 0; j < 16; j++) tot += s_hist[tid*16 + j];
    s_tot[tid] = (int)tot;
    __syncthreads();
    for (int off = 1; off < 256; off <<= 1) {
        int add = (tid + off < 256) ? s_tot[tid + off] : 0;
        __syncthreads();
        s_tot[tid] += add;
        __syncthreads();
    }
    unsigned cum = (tid < 255) ? (unsigned)s_tot[tid + 1] : 0u;
    for (int j = 15; j >= 0; j--) {
        unsigned h = s_hist[tid*16 + j];
        if (cum < 64u && cum + h >= 64u) s_ctl[0] = tid*16 + j;
        cum += h;
    }
    __syncthreads();
    const unsigned T = (unsigned)s_ctl[0];

    for (int i = 0; i < 16; i++) {
        int n = tid + i * 256;
        unsigned long long key = s_keys[n];
        if ((unsigned)(key >> 52) >= T) {
            int slot = atomicAdd(&s_ctl[1], 1);
            if (slot < 1024) s_cand[slot] = key;
        }
    }
    __syncthreads();
    int M = s_ctl[1]; if (M > 1024) M = 1024;
    int P = 64; while (P < M) P <<= 1;
    for (int i = M + tid; i < P; i += 256) s_cand[i] = 0ull;

    for (int k = 2; k <= P; k <<= 1)
        for (int j = k >> 1; j > 0; j >>= 1) {
            __syncthreads();
            for (int i = tid; i < P; i += 256) {
                int ix = i ^ j;
                if (ix > i) {
                    unsigned long long a = s_cand[i], c = s_cand[ix];
                    if (((i & k) == 0) ? (a < c) : (a > c)) { s_cand[i] = c; s_cand[ix] = a; }
                }
            }
        }
    __syncthreads();

    Stage3* st = (Stage3*)s_hist;
    if (tid < 64) {
        int id = 4095 - (int)(unsigned)(s_cand[tid] & 0xFFFFFFFFull);
        st->px[tid] = db[id*3]; st->py[tid] = db[id*3+1]; st->pz[tid] = db[id*3+2];
    }
    __syncthreads();
    if (tid < 64) {
        float sc = fabsf(st->pz[tid] - st->pz[(tid + 63) & 63]);
        st->sk[tid] = ((unsigned long long)__float_as_uint(sc) << 32) | (unsigned)(63 - tid);
    }
    for (int k = 2; k <= 64; k <<= 1)
        for (int j = k >> 1; j > 0; j >>= 1) {
            __syncthreads();
            if (tid < 64) {
                int i = tid, ix = i ^ j;
                if (ix > i) {
                    unsigned long long a = st->sk[i], c = st->sk[ix];
                    if (((i & k) == 0) ? (a < c) : (a > c)) { st->sk[i] = c; st->sk[ix] = a; }
                }
            }
        }
    __syncthreads();

    if (tid < 32) {
        int j = 63 - (int)(unsigned)(st->sk[tid] & 63ull);
        float sx = st->px[j] - cx, sy = st->py[j] - cy, sz = st->pz[j] - cz;
        float w = fabsf(st->pz[j] - cz);
        float m = w;
#pragma unroll
        for (int off = 16; off; off >>= 1) m = fmaxf(m, __shfl_xor_sync(0xffffffffu, m, off));
        float e = expf(w - m);
        float su = e;
#pragma unroll
        for (int off = 16; off; off >>= 1) su += __shfl_xor_sync(0xffffffffu, su, off);
        st->snx[tid] = sx; st->sny[tid] = sy; st->snz[tid] = sz;
        st->zw[tid] = e / su;
        st->tk[tid] = j;
    }
    __syncthreads();

    size_t R0 = (size_t)(b*NSAMP + s) * NK;
    for (int e = tid; e < NK * 68; e += 256) {
        int k = e / 68, c = e - k * 68;
        float val;
        if (c < 3)        val = (c == 0 ? st->snx[k] : (c == 1 ? st->sny[k] : st->snz[k])) * st->zw[k];
        else if (c < 67)  val = feat[((size_t)b*NPTS + st->tk[k]) * 64 + (c - 3)] * st->zw[k];
        else              val = 0.f;
        g_x0[(R0 + k) * 68 + c] = val;
    }
}

// ======== GEMM L0/L1: warp = 8 row-quads x 4 col-octets, 3 LDS phases/k ===
// thread: 4 rows x 8 cols (16 fma2). slice=wid>>1 (32 rows), half=wid&1 (32 cols).
// x LDS.128: 8 distinct contiguous 16B = 1 phase; w 2x LDS.128: 4 distinct
// 16B @32B stride = conflict-free 1 phase each. Bit-exact per-element k-chain.
template<int LAYER>
__global__ __launch_bounds__(256, 3) void gemm01_kernel(const float* __restrict__ W,
                                                        const float* __restrict__ bias) {
    constexpr int KIN   = (LAYER == 0) ? 68 : 64;
    constexpr int KREAL = (LAYER == 0) ? 67 : 64;
    constexpr int OUT   = 64;
    constexpr int RPB   = 128;
    constexpr int XS    = RPB + 4;

    extern __shared__ float sm[];
    float* s_x = sm;                                                  // [KIN][XS]
    unsigned long long* s_w2 = (unsigned long long*)(sm + KIN * XS);  // [KIN][32]

    const float* X = (LAYER == 0) ? g_x0 : g_y0;
    float*       Y = (LAYER == 0) ? g_y0 : g_y1;
    double* sums = g_sums + ((LAYER == 0) ? 0 : 128);

    const int tid = threadIdx.x;
    const int wid = tid >> 5, lane = tid & 31;
    const int slice = wid >> 1, half = wid & 1;
    const int rbase = slice * 32 + 4 * (lane >> 2);
    const int cbase = half * 32 + 8 * (lane & 3);
    const int c2base = half * 16 + 4 * (lane & 3);
    const size_t row0 = (size_t)blockIdx.x * RPB;

    for (int i = tid; i < KIN * 32; i += 256) {
        int k = i >> 5, c2 = i & 31;
        float wa = (k < KREAL) ? W[(2*c2)   * KREAL + k] : 0.f;
        float wb = (k < KREAL) ? W[(2*c2+1) * KREAL + k] : 0.f;
        unsigned long long p;
        asm("mov.b64 %0, {%1, %2};" : "=l"(p) : "r"(__float_as_uint(wa)), "r"(__float_as_uint(wb)));
        s_w2[i] = p;
    }
    for (int i4 = tid; i4 < RPB * (KIN/4); i4 += 256) {
        int r = i4 / (KIN/4), kq = (i4 % (KIN/4)) * 4;
        float4 v = *(const float4*)&X[(row0 + r) * KIN + kq];
        if (LAYER > 0) {
            v.x = fmaxf(fmaf(v.x, __ldg(&g_scale[kq+0]), __ldg(&g_shift[kq+0])), 0.f);
            v.y = fmaxf(fmaf(v.y, __ldg(&g_scale[kq+1]), __ldg(&g_shift[kq+1])), 0.f);
            v.z = fmaxf(fmaf(v.z, __ldg(&g_scale[kq+2]), __ldg(&g_shift[kq+2])), 0.f);
            v.w = fmaxf(fmaf(v.w, __ldg(&g_scale[kq+3]), __ldg(&g_shift[kq+3])), 0.f);
        }
        s_x[(kq+0)*XS + r] = v.x; s_x[(kq+1)*XS + r] = v.y;
        s_x[(kq+2)*XS + r] = v.z; s_x[(kq+3)*XS + r] = v.w;
    }
    __syncthreads();

    unsigned long long acc[4][4];
#pragma unroll
    for (int r = 0; r < 4; r++)
#pragma unroll
        for (int j = 0; j < 4; j++) acc[r][j] = 0ull;

#pragma unroll 4
    for (int k = 0; k < KIN; k++) {
        float4 xq = *(const float4*)(s_x + k * XS + rbase);
        unsigned long long a0 = pk_dup(xq.x), a1 = pk_dup(xq.y),
                           a2 = pk_dup(xq.z), a3 = pk_dup(xq.w);
        ulonglong2 wA = *(const ulonglong2*)(s_w2 + k * 32 + c2base);
        ulonglong2 wB = *(const ulonglong2*)(s_w2 + k * 32 + c2base + 2);
        fma2(acc[0][0], a0, wA.x); fma2(acc[0][1], a0, wA.y);
        fma2(acc[0][2], a0, wB.x); fma2(acc[0][3], a0, wB.y);
        fma2(acc[1][0], a1, wA.x); fma2(acc[1][1], a1, wA.y);
        fma2(acc[1][2], a1, wB.x); fma2(acc[1][3], a1, wB.y);
        fma2(acc[2][0], a2, wA.x); fma2(acc[2][1], a2, wA.y);
        fma2(acc[2][2], a2, wB.x); fma2(acc[2][3], a2, wB.y);
        fma2(acc[3][0], a3, wA.x); fma2(acc[3][1], a3, wA.y);
        fma2(acc[3][2], a3, wB.x); fma2(acc[3][3], a3, wB.y);
    }

    float psum[8], psq[8];
#pragma unroll
    for (int j = 0; j < 8; j++) { psum[j] = 0.f; psq[j] = 0.f; }

#pragma unroll
    for (int r = 0; r < 4; r++) {
        float yv[8];
#pragma unroll
        for (int jp = 0; jp < 4; jp++) unpk(acc[r][jp], yv[2*jp], yv[2*jp+1]);
#pragma unroll
        for (int j = 0; j < 8; j++) {
            yv[j] = yv[j] + __ldg(&bias[cbase + j]);
            psum[j] += yv[j];
            psq[j]  = fmaf(yv[j], yv[j], psq[j]);
        }
        size_t row = row0 + rbase + r;
        float4* dst = (float4*)&Y[row * OUT + cbase];
        dst[0] = make_float4(yv[0], yv[1], yv[2], yv[3]);
        dst[1] = make_float4(yv[4], yv[5], yv[6], yv[7]);
    }
    // reduce over the 8 lanes (stride 4) covering this warp's 32 rows
#pragma unroll
    for (int j = 0; j < 8; j++) {
        psum[j] += __shfl_down_sync(0xffffffffu, psum[j], 16);
        psq[j]  += __shfl_down_sync(0xffffffffu, psq[j],  16);
        psum[j] += __shfl_down_sync(0xffffffffu, psum[j], 8);
        psq[j]  += __shfl_down_sync(0xffffffffu, psq[j],  8);
        psum[j] += __shfl_down_sync(0xffffffffu, psum[j], 4);
        psq[j]  += __shfl_down_sync(0xffffffffu, psq[j],  4);
    }
    if (lane < 4) {
        int cb = half * 32 + 8 * lane;
#pragma unroll
        for (int j = 0; j < 8; j++) {
            atomicAdd(&sums[cb + j],       (double)psum[j]);
            atomicAdd(&sums[OUT + cb + j], (double)psq[j]);
        }
    }
}

// ======== GEMM L2: same geometry, OUT=128, RPB=64, stats + max/min ========
__global__ __launch_bounds__(256, 3) void gemm2_kernel(const float* __restrict__ W,
                                                       const float* __restrict__ bias) {
    constexpr int KIN = 64, OUT = 128, RPB = 64, XS = RPB + 4;

    extern __shared__ float sm[];
    float* s_x = sm;                                                  // [64][68]
    unsigned long long* s_w2 = (unsigned long long*)(sm + KIN * XS);  // [64][64]
    double* sums = g_sums + 256;

    const int tid = threadIdx.x;
    const int wid = tid >> 5, lane = tid & 31;
    const int slice = wid >> 2, quart = wid & 3;     // 2 slices x 32 rows, 4 quarters x 32 cols
    const int rbase = slice * 32 + 4 * (lane >> 2);
    const int cbase = quart * 32 + 8 * (lane & 3);
    const int c2base = quart * 16 + 4 * (lane & 3);
    const size_t row0 = (size_t)blockIdx.x * RPB;

    for (int i = tid; i < KIN * 64; i += 256) {
        int k = i >> 6, c2 = i & 63;
        float wa = W[(2*c2)   * KIN + k];
        float wb = W[(2*c2+1) * KIN + k];
        unsigned long long p;
        asm("mov.b64 %0, {%1, %2};" : "=l"(p) : "r"(__float_as_uint(wa)), "r"(__float_as_uint(wb)));
        s_w2[i] = p;
    }
    for (int i4 = tid; i4 < RPB * (KIN/4); i4 += 256) {
        int r = i4 / (KIN/4), kq = (i4 % (KIN/4)) * 4;
        float4 v = *(const float4*)&g_y1[(row0 + r) * KIN + kq];
        v.x = fmaxf(fmaf(v.x, __ldg(&g_scale[64+kq+0]), __ldg(&g_shift[64+kq+0])), 0.f);
        v.y = fmaxf(fmaf(v.y, __ldg(&g_scale[64+kq+1]), __ldg(&g_shift[64+kq+1])), 0.f);
        v.z = fmaxf(fmaf(v.z, __ldg(&g_scale[64+kq+2]), __ldg(&g_shift[64+kq+2])), 0.f);
        v.w = fmaxf(fmaf(v.w, __ldg(&g_scale[64+kq+3]), __ldg(&g_shift[64+kq+3])), 0.f);
        s_x[(kq+0)*XS + r] = v.x; s_x[(kq+1)*XS + r] = v.y;
        s_x[(kq+2)*XS + r] = v.z; s_x[(kq+3)*XS + r] = v.w;
    }
    __syncthreads();

    unsigned long long acc[4][4];
#pragma unroll
    for (int r = 0; r < 4; r++)
#pragma unroll
        for (int j = 0; j < 4; j++) acc[r][j] = 0ull;

#pragma unroll 4
    for (int k = 0; k < KIN; k++) {
        float4 xq = *(const float4*)(s_x + k * XS + rbase);
        unsigned long long a0 = pk_dup(xq.x), a1 = pk_dup(xq.y),
                           a2 = pk_dup(xq.z), a3 = pk_dup(xq.w);
        ulonglong2 wA = *(const ulonglong2*)(s_w2 + k * 64 + c2base);
        ulonglong2 wB = *(const ulonglong2*)(s_w2 + k * 64 + c2base + 2);
        fma2(acc[0][0], a0, wA.x); fma2(acc[0][1], a0, wA.y);
        fma2(acc[0][2], a0, wB.x); fma2(acc[0][3], a0, wB.y);
        fma2(acc[1][0], a1, wA.x); fma2(acc[1][1], a1, wA.y);
        fma2(acc[1][2], a1, wB.x); fma2(acc[1][3], a1, wB.y);
        fma2(acc[2][0], a2, wA.x); fma2(acc[2][1], a2, wA.y);
        fma2(acc[2][2], a2, wB.x); fma2(acc[2][3], a2, wB.y);
        fma2(acc[3][0], a3, wA.x); fma2(acc[3][1], a3, wA.y);
        fma2(acc[3][2], a3, wB.x); fma2(acc[3][3], a3, wB.y);
    }

    float psum[8], psq[8], tmax[8], tmin[8];
#pragma unroll
    for (int j = 0; j < 8; j++) {
        psum[j] = 0.f; psq[j] = 0.f; tmax[j] = -1e30f; tmin[j] = 1e30f;
    }

#pragma unroll
    for (int r = 0; r < 4; r++) {
        float yv[8];
#pragma unroll
        for (int jp = 0; jp < 4; jp++) unpk(acc[r][jp], yv[2*jp], yv[2*jp+1]);
#pragma unroll
        for (int j = 0; j < 8; j++) {
            yv[j] = yv[j] + __ldg(&bias[cbase + j]);
            psum[j] += yv[j];
            psq[j]  = fmaf(yv[j], yv[j], psq[j]);
            tmax[j] = fmaxf(tmax[j], yv[j]);
            tmin[j] = fminf(tmin[j], yv[j]);
        }
    }
    // reductions over the 8 stride-4 lanes (= this warp's 32 rows = 1 sample)
#pragma unroll
    for (int j = 0; j < 8; j++) {
        psum[j] += __shfl_down_sync(0xffffffffu, psum[j], 16);
        psq[j]  += __shfl_down_sync(0xffffffffu, psq[j],  16);
        tmax[j] = fmaxf(tmax[j], __shfl_down_sync(0xffffffffu, tmax[j], 16));
        tmin[j] = fminf(tmin[j], __shfl_down_sync(0xffffffffu, tmin[j], 16));
        psum[j] += __shfl_down_sync(0xffffffffu, psum[j], 8);
        psq[j]  += __shfl_down_sync(0xffffffffu, psq[j],  8);
        tmax[j] = fmaxf(tmax[j], __shfl_down_sync(0xffffffffu, tmax[j], 8));
        tmin[j] = fminf(tmin[j], __shfl_down_sync(0xffffffffu, tmin[j], 8));
        psum[j] += __shfl_down_sync(0xffffffffu, psum[j], 4);
        psq[j]  += __shfl_down_sync(0xffffffffu, psq[j],  4);
        tmax[j] = fmaxf(tmax[j], __shfl_down_sync(0xffffffffu, tmax[j], 4));
        tmin[j] = fminf(tmin[j], __shfl_down_sync(0xffffffffu, tmin[j], 4));
    }
    if (lane < 4) {
        int cb = quart * 32 + 8 * lane;
#pragma unroll
        for (int j = 0; j < 8; j++) {
            atomicAdd(&sums[cb + j],       (double)psum[j]);
            atomicAdd(&sums[OUT + cb + j], (double)psq[j]);
        }
        size_t samp = row0 / 32 + slice;
        float4* pma = (float4*)&g_ymax[samp * 128 + cb];
        float4* pmi = (float4*)&g_ymin[samp * 128 + cb];
        pma[0] = make_float4(tmax[0], tmax[1], tmax[2], tmax[3]);
        pma[1] = make_float4(tmax[4], tmax[5], tmax[6], tmax[7]);
        pmi[0] = make_float4(tmin[0], tmin[1], tmin[2], tmin[3]);
        pmi[1] = make_float4(tmin[4], tmin[5], tmin[6], tmin[7]);
    }
}

__global__ void finalize_kernel(const float* __restrict__ g, const float* __restrict__ be,
                                int O, int soff, int scoff) {
    int c = threadIdx.x;
    if (c >= O) return;
    double n = (double)NROWS;
    double mean = g_sums[soff + c] / n;
    double var  = g_sums[soff + O + c] / n - mean * mean;
    double sc   = (double)g[c] * rsqrt(var + 1e-5);
    g_scale[scoff + c] = (float)sc;
    g_shift[scoff + c] = (float)((double)be[c] - mean * sc);
}

__global__ __launch_bounds__(128) void maxpool_kernel(float* __restrict__ out) {
    int bs = blockIdx.x, c = threadIdx.x;
    float sc = g_scale[128 + c], sh = g_shift[128 + c];
    float v = (sc >= 0.f) ? g_ymax[(size_t)bs * 128 + c] : g_ymin[(size_t)bs * 128 + c];
    out[OUT_OFF + (size_t)bs * 128 + c] = fmaxf(fmaf(v, sc, sh), 0.f);
}

// ============================ launcher ====================================
extern "C" void kernel_launch(void* const* d_in, const int* in_sizes, int n_in,
                              void* d_out, int out_size) {
    const float* data = (const float*)d_in[0];
    const float* feat = (const float*)d_in[1];
    const int*   initf = (const int*)d_in[2];
    const float* W0 = (const float*)d_in[3];  const float* b0 = (const float*)d_in[4];
    const float* g0 = (const float*)d_in[5];  const float* be0 = (const float*)d_in[6];
    const float* W1 = (const float*)d_in[7];  const float* b1 = (const float*)d_in[8];
    const float* g1 = (const float*)d_in[9];  const float* be1 = (const float*)d_in[10];
    const float* W2 = (const float*)d_in[11]; const float* b2 = (const float*)d_in[12];
    const float* g2 = (const float*)d_in[13]; const float* be2 = (const float*)d_in[14];
    float* out = (float*)d_out;

    const int smf = NPTS * 3 * 4 + 128 * 4;          // fps: 49664
    const int smb = 58368 + 32;                      // build
    const int sm0 = 68*132*4 + 68*32*8;              // 53312
    const int sm1 = 64*132*4 + 64*32*8;              // 50176
    const int sm2 = 64*68*4  + 64*64*8;              // 50176
    cudaFuncSetAttribute((const void*)fps_kernel,       cudaFuncAttributeMaxDynamicSharedMemorySize, smf);
    cudaFuncSetAttribute((const void*)build_kernel,     cudaFuncAttributeMaxDynamicSharedMemorySize, smb);
    cudaFuncSetAttribute((const void*)gemm01_kernel<0>, cudaFuncAttributeMaxDynamicSharedMemorySize, sm0);
    cudaFuncSetAttribute((const void*)gemm01_kernel<1>, cudaFuncAttributeMaxDynamicSharedMemorySize, sm1);
    cudaFuncSetAttribute((const void*)gemm2_kernel,     cudaFuncAttributeMaxDynamicSharedMemorySize, sm2);

    zero_stats_kernel<<<1, 512>>>();
    fps_kernel<<<NBATCH, 1024, smf>>>(data, initf, out);
    build_kernel<<<NBATCH * NSAMP, 256, smb>>>(data, feat);
    gemm01_kernel<0><<<NROWS / 128, 256, sm0>>>(W0, b0);
    finalize_kernel<<<1, 128>>>(g0, be0, 64, 0, 0);
    gemm01_kernel<1><<<NROWS / 128, 256, sm1>>>(W1, b1);
    finalize_kernel<<<1, 128>>>(g1, be1, 64, 128, 64);
    gemm2_kernel<<<NROWS / 64, 256, sm2>>>(W2, b2);
    finalize_kernel<<<1, 128>>>(g2, be2, 128, 256, 128);
    maxpool_kernel<<<NBATCH * NSAMP, 128>>>(out);
}

// round 9
// speedup vs baseline: 1.5690x; 1.5690x over previous
#include <cuda_runtime.h>
#include <math.h>

#define NPTS   4096
#define NBATCH 16
#define NSAMP  1024
#define NK     32
#define NROWS  (NBATCH*NSAMP*NK)      /* 524288 */
#define NSAMPT (NBATCH*NSAMP)         /* 16384  */
#define OUT_OFF (NBATCH*NSAMP*3)      /* 49152  */

// ---------------- device scratch (no allocations allowed) ----------------
__device__ float  g_centroids[NBATCH*NSAMP*3];
__device__ float  g_x0[(size_t)NROWS*68];
__device__ float  g_y0[(size_t)NROWS*64];
__device__ float  g_y1[(size_t)NROWS*64];
__device__ float  g_ymax[(size_t)NSAMPT*128];
__device__ float  g_ymin[(size_t)NSAMPT*128];
__device__ double g_sums[512];
__device__ float  g_scale[256];
__device__ float  g_shift[256];

__global__ void zero_stats_kernel() {
    int t = threadIdx.x;
    if (t < 512) g_sums[t] = 0.0;
}

// ---------------- packed f32x2 helpers (exact RN f32 math) ---------------
__device__ __forceinline__ unsigned long long pk_dup(float x) {
    unsigned long long r; unsigned u = __float_as_uint(x);
    asm("mov.b64 %0, {%1, %1};" : "=l"(r) : "r"(u));
    return r;
}
__device__ __forceinline__ void fma2(unsigned long long& d, unsigned long long a,
                                     unsigned long long b) {
    asm("fma.rn.f32x2 %0, %1, %2, %0;" : "+l"(d) : "l"(a), "l"(b));
}
__device__ __forceinline__ void unpk(unsigned long long v, float& lo, float& hi) {
    unsigned a, b;
    asm("mov.b64 {%0, %1}, %2;" : "=r"(a), "=r"(b) : "l"(v));
    lo = __uint_as_float(a); hi = __uint_as_float(b);
}

// ============================ FPS (round-6 version) ========================
// dist = min(dist, |p-c|^2); far = argmax (first index on tie).
// Points cached in dynamic smem (SoA). One __syncthreads per iteration via
// double-buffered per-warp reduction slots. REDUX (32-bit) reductions:
// max on dist-bits, then max on masked (4095-idx) -> exact first-index tie.
__global__ __launch_bounds__(1024) void fps_kernel(const float* __restrict__ data,
                                                   const int* __restrict__ initf,
                                                   float* __restrict__ out) {
    extern __shared__ float fsm[];
    float* s_px = fsm;
    float* s_py = fsm + NPTS;
    float* s_pz = fsm + 2*NPTS;
    unsigned* s_rd = (unsigned*)(fsm + 3*NPTS);   // 64 (double-buffered)
    unsigned* s_ri = s_rd + 64;

    const int b = blockIdx.x, tid = threadIdx.x;
    const int lane = tid & 31, wid = tid >> 5;
    const float* db = data + (size_t)b * NPTS * 3;

    float px[4], py[4], pz[4], dist[4];
#pragma unroll
    for (int i = 0; i < 4; i++) {
        int n = tid + i * 1024;
        float x = db[n*3+0], y = db[n*3+1], z = db[n*3+2];
        px[i] = x; py[i] = y; pz[i] = z;
        s_px[n] = x; s_py[n] = y; s_pz[n] = z;
        dist[i] = 1e10f;
    }
    int far = __ldg(initf + b);
    __syncthreads();

    for (int s = 0; s < NSAMP; s++) {
        float cx = s_px[far], cy = s_py[far], cz = s_pz[far];
        if (tid == 0) {
            int o = (b*NSAMP + s) * 3;
            out[o] = cx; out[o+1] = cy; out[o+2] = cz;
            g_centroids[o] = cx; g_centroids[o+1] = cy; g_centroids[o+2] = cz;
        }
        unsigned long long best = 0ull;
#pragma unroll
        for (int i = 0; i < 4; i++) {
            float dx = px[i]-cx, dy = py[i]-cy, dz = pz[i]-cz;
            float d = dx*dx + dy*dy + dz*dz;
            dist[i] = fminf(dist[i], d);
            unsigned long long key =
                ((unsigned long long)__float_as_uint(dist[i]) << 32) |
                (unsigned)(4095 - (tid + i*1024));
            best = best > key ? best : key;
        }
        unsigned d32 = (unsigned)(best >> 32);
        unsigned i32 = (unsigned)best;
        unsigned wd = __reduce_max_sync(0xffffffffu, d32);
        unsigned ci = (d32 == wd) ? i32 : 0u;
        unsigned wi = __reduce_max_sync(0xffffffffu, ci);
        int par = (s & 1) * 32;
        if (lane == 0) { s_rd[par + wid] = wd; s_ri[par + wid] = wi; }
        __syncthreads();
        unsigned dv = s_rd[par + lane], iv = s_ri[par + lane];
        unsigned gd = __reduce_max_sync(0xffffffffu, dv);
        unsigned c2 = (dv == gd) ? iv : 0u;
        unsigned gi = __reduce_max_sync(0xffffffffu, c2);
        far = 4095 - (int)gi;
    }
}

// ==================== stage 2+3: top64 -> top32 -> x0 rows ================
struct Stage3 {
    float px[64], py[64], pz[64];
    unsigned long long sk[64];
    float snx[32], sny[32], snz[32], zw[32];
    int   tk[32];
};

__device__ __forceinline__ unsigned ord_f32(float v) {
    unsigned u = __float_as_uint(v);
    return (u & 0x80000000u) ? ~u : (u | 0x80000000u);
}

// Bit-exact replication of the reference square-dist (verified passing):
__device__ __forceinline__ float sqdist_ref(float cx, float cy, float cz, float an2,
                                            float x, float y, float z) {
    float e   = __fmaf_rn(cz, z, __fmaf_rn(cy, y, __fmul_rn(cx, x)));
    float bn2 = __fadd_rn(__fadd_rn(__fmul_rn(x, x), __fmul_rn(y, y)), __fmul_rn(z, z));
    return __fadd_rn(__fadd_rn(__fmul_rn(-2.f, e), an2), bn2);
}

__global__ __launch_bounds__(256) void build_kernel(const float* __restrict__ data,
                                                    const float* __restrict__ feat) {
    extern __shared__ char bsm[];
    unsigned long long* s_keys = (unsigned long long*)bsm;            // 4096 * 8
    unsigned int*       s_hist = (unsigned int*)(bsm + 32768);        // 4096 * 4
    unsigned long long* s_cand = (unsigned long long*)(bsm + 49152);  // 1024 * 8
    int*                s_tot  = (int*)(bsm + 57344);                 // 256 * 4
    int*                s_ctl  = (int*)(bsm + 58368);                 // [0]=T [1]=m

    const int tid = threadIdx.x;
    const int b = blockIdx.x >> 10, s = blockIdx.x & 1023;
    const float* db = data + (size_t)b * NPTS * 3;
    const int co = (b*NSAMP + s) * 3;
    const float cx = g_centroids[co], cy = g_centroids[co+1], cz = g_centroids[co+2];
    const float an2 = __fadd_rn(__fadd_rn(__fmul_rn(cx, cx), __fmul_rn(cy, cy)),
                                __fmul_rn(cz, cz));

    for (int i = tid; i < 4096; i += 256) s_hist[i] = 0u;
    if (tid == 0) s_ctl[1] = 0;
    __syncthreads();

    // pass 1: compute keys once, cache in smem, histogram top 12 bits
    for (int i = 0; i < 16; i++) {
        int n = tid + i * 256;
        float x = db[n*3], y = db[n*3+1], z = db[n*3+2];
        float v = sqdist_ref(cx, cy, cz, an2, x, y, z);
        unsigned u = ord_f32(v);
        s_keys[n] = ((unsigned long long)u << 32) | (unsigned)(4095 - n);
        atomicAdd(&s_hist[u >> 20], 1u);
    }
    __syncthreads();

    // suffix counts over 256 chunks of 16 bins
    unsigned tot = 0;
    for (int j = 0; j < 16; j++) tot += s_hist[tid*16 + j];
    s_tot[tid] = (int)tot;
    __syncthreads();
    for (int off = 1; off < 256; off <<= 1) {
        int add = (tid + off < 256) ? s_tot[tid + off] : 0;
        __syncthreads();
        s_tot[tid] += add;
        __syncthreads();
    }
    unsigned cum = (tid < 255) ? (unsigned)s_tot[tid + 1] : 0u;
    for (int j = 15; j >= 0; j--) {
        unsigned h = s_hist[tid*16 + j];
        if (cum < 64u && cum + h >= 64u) s_ctl[0] = tid*16 + j;
        cum += h;
    }
    __syncthreads();
    const unsigned T = (unsigned)s_ctl[0];

    // pass 2: pure smem scan, push candidates with bin >= T
    for (int i = 0; i < 16; i++) {
        int n = tid + i * 256;
        unsigned long long key = s_keys[n];
        if ((unsigned)(key >> 52) >= T) {
            int slot = atomicAdd(&s_ctl[1], 1);
            if (slot < 1024) s_cand[slot] = key;
        }
    }
    __syncthreads();
    int M = s_ctl[1]; if (M > 1024) M = 1024;
    int P = 64; while (P < M) P <<= 1;
    for (int i = M + tid; i < P; i += 256) s_cand[i] = 0ull;

    // bitonic sort descending
    for (int k = 2; k <= P; k <<= 1)
        for (int j = k >> 1; j > 0; j >>= 1) {
            __syncthreads();
            for (int i = tid; i < P; i += 256) {
                int ix = i ^ j;
                if (ix > i) {
                    unsigned long long a = s_cand[i], c = s_cand[ix];
                    if (((i & k) == 0) ? (a < c) : (a > c)) { s_cand[i] = c; s_cand[ix] = a; }
                }
            }
        }
    __syncthreads();

    Stage3* st = (Stage3*)s_hist;   // alias dead histogram
    if (tid < 64) {
        int id = 4095 - (int)(unsigned)(s_cand[tid] & 0xFFFFFFFFull);
        st->px[tid] = db[id*3]; st->py[tid] = db[id*3+1]; st->pz[tid] = db[id*3+2];
    }
    __syncthreads();
    if (tid < 64) {
        float sc = fabsf(st->pz[tid] - st->pz[(tid + 63) & 63]);   // roll(+1)
        st->sk[tid] = ((unsigned long long)__float_as_uint(sc) << 32) | (unsigned)(63 - tid);
    }
    for (int k = 2; k <= 64; k <<= 1)
        for (int j = k >> 1; j > 0; j >>= 1) {
            __syncthreads();
            if (tid < 64) {
                int i = tid, ix = i ^ j;
                if (ix > i) {
                    unsigned long long a = st->sk[i], c = st->sk[ix];
                    if (((i & k) == 0) ? (a < c) : (a > c)) { st->sk[i] = c; st->sk[ix] = a; }
                }
            }
        }
    __syncthreads();

    if (tid < 32) {
        int j = 63 - (int)(unsigned)(st->sk[tid] & 63ull);   // tki
        float sx = st->px[j] - cx, sy = st->py[j] - cy, sz = st->pz[j] - cz;
        float w = fabsf(st->pz[j] - cz);
        float m = w;
#pragma unroll
        for (int off = 16; off; off >>= 1) m = fmaxf(m, __shfl_xor_sync(0xffffffffu, m, off));
        float e = expf(w - m);
        float su = e;
#pragma unroll
        for (int off = 16; off; off >>= 1) su += __shfl_xor_sync(0xffffffffu, su, off);
        st->snx[tid] = sx; st->sny[tid] = sy; st->snz[tid] = sz;
        st->zw[tid] = e / su;
        st->tk[tid] = j;
    }
    __syncthreads();

    size_t R0 = (size_t)(b*NSAMP + s) * NK;
    for (int e = tid; e < NK * 68; e += 256) {
        int k = e / 68, c = e - k * 68;
        float val;
        if (c < 3)        val = (c == 0 ? st->snx[k] : (c == 1 ? st->sny[k] : st->snz[k])) * st->zw[k];
        else if (c < 67)  val = feat[((size_t)b*NPTS + st->tk[k]) * 64 + (c - 3)] * st->zw[k];
        else              val = 0.f;
        g_x0[(R0 + k) * 68 + c] = val;
    }
}

// ==================== GEMM layers 0/1 (round-5 verbatim, 219us) ===========
template<int LAYER>
__global__ __launch_bounds__(256) void gemm01_kernel(const float* __restrict__ W,
                                                     const float* __restrict__ bias) {
    constexpr int KIN   = (LAYER == 0) ? 68 : 64;
    constexpr int KREAL = (LAYER == 0) ? 67 : 64;
    constexpr int OUT   = 64;
    constexpr int RPB   = 128;
    constexpr int XS    = RPB + 4;

    extern __shared__ float sm[];
    float* s_x = sm;                 // [KIN][XS]
    float* s_w = sm + KIN * XS;      // [KIN][OUT]

    const float* X = (LAYER == 0) ? g_x0 : g_y0;
    float*       Y = (LAYER == 0) ? g_y0 : g_y1;
    double* sums = g_sums + ((LAYER == 0) ? 0 : 128);

    const int tid = threadIdx.x;
    const int cg = tid >> 5, rg = tid & 31;    // 8 col-groups x 8 cols, 32 row-groups x 4 rows
    const size_t row0 = (size_t)blockIdx.x * RPB;

    for (int i = tid; i < KIN * OUT; i += 256) {
        int k = i / OUT, c = i - k * OUT;
        s_w[k * OUT + c] = (k < KREAL) ? W[c * KREAL + k] : 0.f;
    }
    for (int i = tid; i < RPB * KIN; i += 256) {
        int r = i / KIN, k = i - r * KIN;
        float v = X[(row0 + r) * KIN + k];
        if (LAYER > 0)
            v = fmaxf(fmaf(v, __ldg(&g_scale[k]), __ldg(&g_shift[k])), 0.f);
        s_x[k * XS + r] = v;
    }
    __syncthreads();

    unsigned long long acc[4][4];
#pragma unroll
    for (int i = 0; i < 4; i++)
#pragma unroll
        for (int j = 0; j < 4; j++) acc[i][j] = 0ull;

    const unsigned long long* s_w2 = (const unsigned long long*)s_w;
#pragma unroll 4
    for (int k = 0; k < KIN; k++) {
        float4 xq = *(const float4*)(s_x + k * XS + 4 * rg);
        unsigned long long a0 = pk_dup(xq.x), a1 = pk_dup(xq.y),
                           a2 = pk_dup(xq.z), a3 = pk_dup(xq.w);
        ulonglong2 b01 = *(const ulonglong2*)(s_w2 + ((k * OUT + cg * 8) >> 1));
        ulonglong2 b23 = *(const ulonglong2*)(s_w2 + ((k * OUT + cg * 8) >> 1) + 2);
        fma2(acc[0][0], a0, b01.x); fma2(acc[0][1], a0, b01.y);
        fma2(acc[0][2], a0, b23.x); fma2(acc[0][3], a0, b23.y);
        fma2(acc[1][0], a1, b01.x); fma2(acc[1][1], a1, b01.y);
        fma2(acc[1][2], a1, b23.x); fma2(acc[1][3], a1, b23.y);
        fma2(acc[2][0], a2, b01.x); fma2(acc[2][1], a2, b01.y);
        fma2(acc[2][2], a2, b23.x); fma2(acc[2][3], a2, b23.y);
        fma2(acc[3][0], a3, b01.x); fma2(acc[3][1], a3, b01.y);
        fma2(acc[3][2], a3, b23.x); fma2(acc[3][3], a3, b23.y);
    }

    float bl[8];
#pragma unroll
    for (int j = 0; j < 8; j++) bl[j] = bias[cg * 8 + j];
    float psum[8], psq[8];
#pragma unroll
    for (int j = 0; j < 8; j++) { psum[j] = 0.f; psq[j] = 0.f; }

#pragma unroll
    for (int r = 0; r < 4; r++) {
        float yv[8];
#pragma unroll
        for (int jp = 0; jp < 4; jp++) unpk(acc[r][jp], yv[2*jp], yv[2*jp+1]);
#pragma unroll
        for (int j = 0; j < 8; j++) {
            yv[j] = yv[j] + bl[j];
            psum[j] += yv[j];
            psq[j]  = fmaf(yv[j], yv[j], psq[j]);
        }
        size_t row = row0 + 4 * rg + r;
        float4* dst = (float4*)&Y[row * OUT + cg * 8];
        dst[0] = make_float4(yv[0], yv[1], yv[2], yv[3]);
        dst[1] = make_float4(yv[4], yv[5], yv[6], yv[7]);
    }
#pragma unroll
    for (int j = 0; j < 8; j++) {
#pragma unroll
        for (int off = 16; off; off >>= 1) {
            psum[j] += __shfl_down_sync(0xffffffffu, psum[j], off);
            psq[j]  += __shfl_down_sync(0xffffffffu, psq[j],  off);
        }
    }
    if ((tid & 31) == 0) {
#pragma unroll
        for (int j = 0; j < 8; j++) {
            atomicAdd(&sums[cg * 8 + j],       (double)psum[j]);
            atomicAdd(&sums[OUT + cg * 8 + j], (double)psq[j]);
        }
    }
}

// ==================== GEMM layer 2 (round-5 verbatim) =====================
__global__ __launch_bounds__(256) void gemm2_kernel(const float* __restrict__ W,
                                                    const float* __restrict__ bias) {
    constexpr int KIN = 64, OUT = 128, RPB = 64, XS = RPB + 4;

    extern __shared__ float sm[];
    float* s_x = sm;                 // [64][68]
    float* s_w = sm + KIN * XS;      // [64][128]
    double* sums = g_sums + 256;

    const int tid = threadIdx.x;
    const int cg = tid >> 4, rg = tid & 15;    // 16 col-groups x 8 cols, 16 row-groups x 4 rows
    const size_t row0 = (size_t)blockIdx.x * RPB;

    for (int i = tid; i < KIN * OUT; i += 256) {
        int k = i / OUT, c = i - k * OUT;
        s_w[k * OUT + c] = W[c * KIN + k];
    }
    for (int i = tid; i < RPB * KIN; i += 256) {
        int r = i / KIN, k = i - r * KIN;
        float v = g_y1[(row0 + r) * KIN + k];
        v = fmaxf(fmaf(v, __ldg(&g_scale[64 + k]), __ldg(&g_shift[64 + k])), 0.f);
        s_x[k * XS + r] = v;
    }
    __syncthreads();

    unsigned long long acc[4][4];
#pragma unroll
    for (int i = 0; i < 4; i++)
#pragma unroll
        for (int j = 0; j < 4; j++) acc[i][j] = 0ull;

    const unsigned long long* s_w2 = (const unsigned long long*)s_w;
#pragma unroll 4
    for (int k = 0; k < KIN; k++) {
        float4 xq = *(const float4*)(s_x + k * XS + 4 * rg);
        unsigned long long a0 = pk_dup(xq.x), a1 = pk_dup(xq.y),
                           a2 = pk_dup(xq.z), a3 = pk_dup(xq.w);
        ulonglong2 b01 = *(const ulonglong2*)(s_w2 + ((k * OUT + cg * 8) >> 1));
        ulonglong2 b23 = *(const ulonglong2*)(s_w2 + ((k * OUT + cg * 8) >> 1) + 2);
        fma2(acc[0][0], a0, b01.x); fma2(acc[0][1], a0, b01.y);
        fma2(acc[0][2], a0, b23.x); fma2(acc[0][3], a0, b23.y);
        fma2(acc[1][0], a1, b01.x); fma2(acc[1][1], a1, b01.y);
        fma2(acc[1][2], a1, b23.x); fma2(acc[1][3], a1, b23.y);
        fma2(acc[2][0], a2, b01.x); fma2(acc[2][1], a2, b01.y);
        fma2(acc[2][2], a2, b23.x); fma2(acc[2][3], a2, b23.y);
        fma2(acc[3][0], a3, b01.x); fma2(acc[3][1], a3, b01.y);
        fma2(acc[3][2], a3, b23.x); fma2(acc[3][3], a3, b23.y);
    }

    float bl[8];
#pragma unroll
    for (int j = 0; j < 8; j++) bl[j] = bias[cg * 8 + j];
    float psum[8], psq[8], tmax[8], tmin[8];
#pragma unroll
    for (int j = 0; j < 8; j++) {
        psum[j] = 0.f; psq[j] = 0.f; tmax[j] = -1e30f; tmin[j] = 1e30f;
    }

#pragma unroll
    for (int r = 0; r < 4; r++) {
        float yv[8];
#pragma unroll
        for (int jp = 0; jp < 4; jp++) unpk(acc[r][jp], yv[2*jp], yv[2*jp+1]);
#pragma unroll
        for (int j = 0; j < 8; j++) {
            yv[j] = yv[j] + bl[j];
            psum[j] += yv[j];
            psq[j]  = fmaf(yv[j], yv[j], psq[j]);
            tmax[j] = fmaxf(tmax[j], yv[j]);
            tmin[j] = fminf(tmin[j], yv[j]);
        }
    }
    // stats reduce over the 16 threads sharing this col-group (width-16)
#pragma unroll
    for (int j = 0; j < 8; j++) {
#pragma unroll
        for (int off = 8; off; off >>= 1) {
            psum[j] += __shfl_down_sync(0xffffffffu, psum[j], off, 16);
            psq[j]  += __shfl_down_sync(0xffffffffu, psq[j],  off, 16);
        }
    }
    if (rg == 0) {
#pragma unroll
        for (int j = 0; j < 8; j++) {
            atomicAdd(&sums[cg * 8 + j],       (double)psum[j]);
            atomicAdd(&sums[OUT + cg * 8 + j], (double)psq[j]);
        }
    }
    // max/min reduce over the 8 threads of each 32-row sample group (width-8)
#pragma unroll
    for (int j = 0; j < 8; j++) {
#pragma unroll
        for (int off = 4; off; off >>= 1) {
            tmax[j] = fmaxf(tmax[j], __shfl_down_sync(0xffffffffu, tmax[j], off, 8));
            tmin[j] = fminf(tmin[j], __shfl_down_sync(0xffffffffu, tmin[j], off, 8));
        }
    }
    if ((rg & 7) == 0) {
        size_t samp = row0 / 32 + (rg >> 3);
        float* pma = &g_ymax[samp * 128 + cg * 8];
        float* pmi = &g_ymin[samp * 128 + cg * 8];
        ((float4*)pma)[0] = make_float4(tmax[0], tmax[1], tmax[2], tmax[3]);
        ((float4*)pma)[1] = make_float4(tmax[4], tmax[5], tmax[6], tmax[7]);
        ((float4*)pmi)[0] = make_float4(tmin[0], tmin[1], tmin[2], tmin[3]);
        ((float4*)pmi)[1] = make_float4(tmin[4], tmin[5], tmin[6], tmin[7]);
    }
}

__global__ void finalize_kernel(const float* __restrict__ g, const float* __restrict__ be,
                                int O, int soff, int scoff) {
    int c = threadIdx.x;
    if (c >= O) return;
    double n = (double)NROWS;
    double mean = g_sums[soff + c] / n;
    double var  = g_sums[soff + O + c] / n - mean * mean;
    double sc   = (double)g[c] * rsqrt(var + 1e-5);
    g_scale[scoff + c] = (float)sc;
    g_shift[scoff + c] = (float)((double)be[c] - mean * sc);
}

// maxpool via pre-reduced max/min: relu(fma(y,sc,sh)) monotone in y for
// fixed sign(sc) -> exact.
__global__ __launch_bounds__(128) void maxpool_kernel(float* __restrict__ out) {
    int bs = blockIdx.x, c = threadIdx.x;
    float sc = g_scale[128 + c], sh = g_shift[128 + c];
    float v = (sc >= 0.f) ? g_ymax[(size_t)bs * 128 + c] : g_ymin[(size_t)bs * 128 + c];
    out[OUT_OFF + (size_t)bs * 128 + c] = fmaxf(fmaf(v, sc, sh), 0.f);
}

// ============================ launcher ====================================
extern "C" void kernel_launch(void* const* d_in, const int* in_sizes, int n_in,
                              void* d_out, int out_size) {
    const float* data = (const float*)d_in[0];
    const float* feat = (const float*)d_in[1];
    const int*   initf = (const int*)d_in[2];
    const float* W0 = (const float*)d_in[3];  const float* b0 = (const float*)d_in[4];
    const float* g0 = (const float*)d_in[5];  const float* be0 = (const float*)d_in[6];
    const float* W1 = (const float*)d_in[7];  const float* b1 = (const float*)d_in[8];
    const float* g1 = (const float*)d_in[9];  const float* be1 = (const float*)d_in[10];
    const float* W2 = (const float*)d_in[11]; const float* b2 = (const float*)d_in[12];
    const float* g2 = (const float*)d_in[13]; const float* be2 = (const float*)d_in[14];
    float* out = (float*)d_out;

    const int smf = NPTS * 3 * 4 + 128 * 4;          // fps: 49664
    const int smb = 58368 + 32;                      // build
    const int sm0 = (68*132 + 68*64) * 4;            // 53312
    const int sm1 = (64*132 + 64*64) * 4;            // 50176
    const int sm2 = (64*68 + 64*128) * 4;            // 50176
    cudaFuncSetAttribute((const void*)fps_kernel,       cudaFuncAttributeMaxDynamicSharedMemorySize, smf);
    cudaFuncSetAttribute((const void*)build_kernel,     cudaFuncAttributeMaxDynamicSharedMemorySize, smb);
    cudaFuncSetAttribute((const void*)gemm01_kernel<0>, cudaFuncAttributeMaxDynamicSharedMemorySize, sm0);
    cudaFuncSetAttribute((const void*)gemm01_kernel<1>, cudaFuncAttributeMaxDynamicSharedMemorySize, sm1);
    cudaFuncSetAttribute((const void*)gemm2_kernel,     cudaFuncAttributeMaxDynamicSharedMemorySize, sm2);

    zero_stats_kernel<<<1, 512>>>();
    fps_kernel<<<NBATCH, 1024, smf>>>(data, initf, out);
    build_kernel<<<NBATCH * NSAMP, 256, smb>>>(data, feat);
    gemm01_kernel<0><<<NROWS / 128, 256, sm0>>>(W0, b0);
    finalize_kernel<<<1, 128>>>(g0, be0, 64, 0, 0);
    gemm01_kernel<1><<<NROWS / 128, 256, sm1>>>(W1, b1);
    finalize_kernel<<<1, 128>>>(g1, be1, 64, 128, 64);
    gemm2_kernel<<<NROWS / 64, 256, sm2>>>(W2, b2);
    finalize_kernel<<<1, 128>>>(g2, be2, 128, 256, 128);
    maxpool_kernel<<<NBATCH * NSAMP, 128>>>(out);
}

// round 10
// speedup vs baseline: 1.6825x; 1.0723x over previous
#include <cuda_runtime.h>
#include <math.h>

#define NPTS   4096
#define NBATCH 16
#define NSAMP  1024
#define NK     32
#define NROWS  (NBATCH*NSAMP*NK)      /* 524288 */
#define NSAMPT (NBATCH*NSAMP)         /* 16384  */
#define OUT_OFF (NBATCH*NSAMP*3)      /* 49152  */

// ---------------- device scratch (no allocations allowed) ----------------
__device__ float  g_centroids[NBATCH*NSAMP*3];
__device__ float  g_x0[(size_t)NROWS*68];
__device__ float  g_y0[(size_t)NROWS*64];
__device__ float  g_y1[(size_t)NROWS*64];
__device__ float  g_ymax[(size_t)NSAMPT*128];
__device__ float  g_ymin[(size_t)NSAMPT*128];
__device__ double g_sums[512];
__device__ float  g_scale[256];
__device__ float  g_shift[256];

__global__ void zero_stats_kernel() {
    int t = threadIdx.x;
    if (t < 512) g_sums[t] = 0.0;
}

// no-op: shifts the fixed-position ncu capture onto build_kernel
__global__ void probe_kernel() {}

// ---------------- packed f32x2 helpers (exact RN f32 math) ---------------
__device__ __forceinline__ unsigned long long pk_dup(float x) {
    unsigned long long r; unsigned u = __float_as_uint(x);
    asm("mov.b64 %0, {%1, %1};" : "=l"(r) : "r"(u));
    return r;
}
__device__ __forceinline__ void fma2(unsigned long long& d, unsigned long long a,
                                     unsigned long long b) {
    asm("fma.rn.f32x2 %0, %1, %2, %0;" : "+l"(d) : "l"(a), "l"(b));
}
__device__ __forceinline__ void unpk(unsigned long long v, float& lo, float& hi) {
    unsigned a, b;
    asm("mov.b64 {%0, %1}, %2;" : "=r"(a), "=r"(b) : "l"(v));
    lo = __uint_as_float(a); hi = __uint_as_float(b);
}

// ============================ FPS (REDUX version, banked win) ==============
__global__ __launch_bounds__(1024) void fps_kernel(const float* __restrict__ data,
                                                   const int* __restrict__ initf,
                                                   float* __restrict__ out) {
    extern __shared__ float fsm[];
    float* s_px = fsm;
    float* s_py = fsm + NPTS;
    float* s_pz = fsm + 2*NPTS;
    unsigned* s_rd = (unsigned*)(fsm + 3*NPTS);   // 64 (double-buffered)
    unsigned* s_ri = s_rd + 64;

    const int b = blockIdx.x, tid = threadIdx.x;
    const int lane = tid & 31, wid = tid >> 5;
    const float* db = data + (size_t)b * NPTS * 3;

    float px[4], py[4], pz[4], dist[4];
#pragma unroll
    for (int i = 0; i < 4; i++) {
        int n = tid + i * 1024;
        float x = db[n*3+0], y = db[n*3+1], z = db[n*3+2];
        px[i] = x; py[i] = y; pz[i] = z;
        s_px[n] = x; s_py[n] = y; s_pz[n] = z;
        dist[i] = 1e10f;
    }
    int far = __ldg(initf + b);
    __syncthreads();

    for (int s = 0; s < NSAMP; s++) {
        float cx = s_px[far], cy = s_py[far], cz = s_pz[far];
        if (tid == 0) {
            int o = (b*NSAMP + s) * 3;
            out[o] = cx; out[o+1] = cy; out[o+2] = cz;
            g_centroids[o] = cx; g_centroids[o+1] = cy; g_centroids[o+2] = cz;
        }
        unsigned long long best = 0ull;
#pragma unroll
        for (int i = 0; i < 4; i++) {
            float dx = px[i]-cx, dy = py[i]-cy, dz = pz[i]-cz;
            float d = dx*dx + dy*dy + dz*dz;
            dist[i] = fminf(dist[i], d);
            unsigned long long key =
                ((unsigned long long)__float_as_uint(dist[i]) << 32) |
                (unsigned)(4095 - (tid + i*1024));
            best = best > key ? best : key;
        }
        unsigned d32 = (unsigned)(best >> 32);
        unsigned i32 = (unsigned)best;
        unsigned wd = __reduce_max_sync(0xffffffffu, d32);
        unsigned ci = (d32 == wd) ? i32 : 0u;
        unsigned wi = __reduce_max_sync(0xffffffffu, ci);
        int par = (s & 1) * 32;
        if (lane == 0) { s_rd[par + wid] = wd; s_ri[par + wid] = wi; }
        __syncthreads();
        unsigned dv = s_rd[par + lane], iv = s_ri[par + lane];
        unsigned gd = __reduce_max_sync(0xffffffffu, dv);
        unsigned c2 = (dv == gd) ? iv : 0u;
        unsigned gi = __reduce_max_sync(0xffffffffu, c2);
        far = 4095 - (int)gi;
    }
}

// ==================== stage 2+3: top64 -> top32 -> x0 rows ================
struct Stage3 {
    float px[64], py[64], pz[64];
    unsigned long long sk[64];
    float snx[32], sny[32], snz[32], zw[32];
    int   tk[32];
};

__device__ __forceinline__ unsigned ord_f32(float v) {
    unsigned u = __float_as_uint(v);
    return (u & 0x80000000u) ? ~u : (u | 0x80000000u);
}

// Bit-exact replication of the reference square-dist (verified passing):
__device__ __forceinline__ float sqdist_ref(float cx, float cy, float cz, float an2,
                                            float x, float y, float z) {
    float e   = __fmaf_rn(cz, z, __fmaf_rn(cy, y, __fmul_rn(cx, x)));
    float bn2 = __fadd_rn(__fadd_rn(__fmul_rn(x, x), __fmul_rn(y, y)), __fmul_rn(z, z));
    return __fadd_rn(__fadd_rn(__fmul_rn(-2.f, e), an2), bn2);
}

__global__ __launch_bounds__(256) void build_kernel(const float* __restrict__ data,
                                                    const float* __restrict__ feat) {
    extern __shared__ char bsm[];
    unsigned long long* s_keys = (unsigned long long*)bsm;            // 4096 * 8
    unsigned int*       s_hist = (unsigned int*)(bsm + 32768);        // 4096 * 4
    unsigned long long* s_cand = (unsigned long long*)(bsm + 49152);  // 1024 * 8
    int*                s_tot  = (int*)(bsm + 57344);                 // 256 * 4
    int*                s_ctl  = (int*)(bsm + 58368);                 // [0]=T [1]=m

    const int tid = threadIdx.x;
    const int b = blockIdx.x >> 10, s = blockIdx.x & 1023;
    const float* db = data + (size_t)b * NPTS * 3;
    const int co = (b*NSAMP + s) * 3;
    const float cx = g_centroids[co], cy = g_centroids[co+1], cz = g_centroids[co+2];
    const float an2 = __fadd_rn(__fadd_rn(__fmul_rn(cx, cx), __fmul_rn(cy, cy)),
                                __fmul_rn(cz, cz));

    for (int i = tid; i < 4096; i += 256) s_hist[i] = 0u;
    if (tid == 0) s_ctl[1] = 0;
    __syncthreads();

    // pass 1: compute keys once, cache in smem, histogram top 12 bits
    for (int i = 0; i < 16; i++) {
        int n = tid + i * 256;
        float x = db[n*3], y = db[n*3+1], z = db[n*3+2];
        float v = sqdist_ref(cx, cy, cz, an2, x, y, z);
        unsigned u = ord_f32(v);
        s_keys[n] = ((unsigned long long)u << 32) | (unsigned)(4095 - n);
        atomicAdd(&s_hist[u >> 20], 1u);
    }
    __syncthreads();

    // suffix counts over 256 chunks of 16 bins
    unsigned tot = 0;
    for (int j = 0; j < 16; j++) tot += s_hist[tid*16 + j];
    s_tot[tid] = (int)tot;
    __syncthreads();
    for (int off = 1; off < 256; off <<= 1) {
        int add = (tid + off < 256) ? s_tot[tid + off] : 0;
        __syncthreads();
        s_tot[tid] += add;
        __syncthreads();
    }
    unsigned cum = (tid < 255) ? (unsigned)s_tot[tid + 1] : 0u;
    for (int j = 15; j >= 0; j--) {
        unsigned h = s_hist[tid*16 + j];
        if (cum < 64u && cum + h >= 64u) s_ctl[0] = tid*16 + j;
        cum += h;
    }
    __syncthreads();
    const unsigned T = (unsigned)s_ctl[0];

    // pass 2: pure smem scan, push candidates with bin >= T
    for (int i = 0; i < 16; i++) {
        int n = tid + i * 256;
        unsigned long long key = s_keys[n];
        if ((unsigned)(key >> 52) >= T) {
            int slot = atomicAdd(&s_ctl[1], 1);
            if (slot < 1024) s_cand[slot] = key;
        }
    }
    __syncthreads();
    int M = s_ctl[1]; if (M > 1024) M = 1024;
    int P = 64; while (P < M) P <<= 1;
    for (int i = M + tid; i < P; i += 256) s_cand[i] = 0ull;

    // bitonic sort descending
    for (int k = 2; k <= P; k <<= 1)
        for (int j = k >> 1; j > 0; j >>= 1) {
            __syncthreads();
            for (int i = tid; i < P; i += 256) {
                int ix = i ^ j;
                if (ix > i) {
                    unsigned long long a = s_cand[i], c = s_cand[ix];
                    if (((i & k) == 0) ? (a < c) : (a > c)) { s_cand[i] = c; s_cand[ix] = a; }
                }
            }
        }
    __syncthreads();

    Stage3* st = (Stage3*)s_hist;   // alias dead histogram
    if (tid < 64) {
        int id = 4095 - (int)(unsigned)(s_cand[tid] & 0xFFFFFFFFull);
        st->px[tid] = db[id*3]; st->py[tid] = db[id*3+1]; st->pz[tid] = db[id*3+2];
    }
    __syncthreads();
    if (tid < 64) {
        float sc = fabsf(st->pz[tid] - st->pz[(tid + 63) & 63]);   // roll(+1)
        st->sk[tid] = ((unsigned long long)__float_as_uint(sc) << 32) | (unsigned)(63 - tid);
    }
    for (int k = 2; k <= 64; k <<= 1)
        for (int j = k >> 1; j > 0; j >>= 1) {
            __syncthreads();
            if (tid < 64) {
                int i = tid, ix = i ^ j;
                if (ix > i) {
                    unsigned long long a = st->sk[i], c = st->sk[ix];
                    if (((i & k) == 0) ? (a < c) : (a > c)) { st->sk[i] = c; st->sk[ix] = a; }
                }
            }
        }
    __syncthreads();

    if (tid < 32) {
        int j = 63 - (int)(unsigned)(st->sk[tid] & 63ull);   // tki
        float sx = st->px[j] - cx, sy = st->py[j] - cy, sz = st->pz[j] - cz;
        float w = fabsf(st->pz[j] - cz);
        float m = w;
#pragma unroll
        for (int off = 16; off; off >>= 1) m = fmaxf(m, __shfl_xor_sync(0xffffffffu, m, off));
        float e = expf(w - m);
        float su = e;
#pragma unroll
        for (int off = 16; off; off >>= 1) su += __shfl_xor_sync(0xffffffffu, su, off);
        st->snx[tid] = sx; st->sny[tid] = sy; st->snz[tid] = sz;
        st->zw[tid] = e / su;
        st->tk[tid] = j;
    }
    __syncthreads();

    size_t R0 = (size_t)(b*NSAMP + s) * NK;
    for (int e = tid; e < NK * 68; e += 256) {
        int k = e / 68, c = e - k * 68;
        float val;
        if (c < 3)        val = (c == 0 ? st->snx[k] : (c == 1 ? st->sny[k] : st->snz[k])) * st->zw[k];
        else if (c < 67)  val = feat[((size_t)b*NPTS + st->tk[k]) * 64 + (c - 3)] * st->zw[k];
        else              val = 0.f;
        g_x0[(R0 + k) * 68 + c] = val;
    }
}

// ==================== GEMM layers 0/1 (round-5 verbatim, 219us) ===========
template<int LAYER>
__global__ __launch_bounds__(256) void gemm01_kernel(const float* __restrict__ W,
                                                     const float* __restrict__ bias) {
    constexpr int KIN   = (LAYER == 0) ? 68 : 64;
    constexpr int KREAL = (LAYER == 0) ? 67 : 64;
    constexpr int OUT   = 64;
    constexpr int RPB   = 128;
    constexpr int XS    = RPB + 4;

    extern __shared__ float sm[];
    float* s_x = sm;                 // [KIN][XS]
    float* s_w = sm + KIN * XS;      // [KIN][OUT]

    const float* X = (LAYER == 0) ? g_x0 : g_y0;
    float*       Y = (LAYER == 0) ? g_y0 : g_y1;
    double* sums = g_sums + ((LAYER == 0) ? 0 : 128);

    const int tid = threadIdx.x;
    const int cg = tid >> 5, rg = tid & 31;
    const size_t row0 = (size_t)blockIdx.x * RPB;

    for (int i = tid; i < KIN * OUT; i += 256) {
        int k = i / OUT, c = i - k * OUT;
        s_w[k * OUT + c] = (k < KREAL) ? W[c * KREAL + k] : 0.f;
    }
    for (int i = tid; i < RPB * KIN; i += 256) {
        int r = i / KIN, k = i - r * KIN;
        float v = X[(row0 + r) * KIN + k];
        if (LAYER > 0)
            v = fmaxf(fmaf(v, __ldg(&g_scale[k]), __ldg(&g_shift[k])), 0.f);
        s_x[k * XS + r] = v;
    }
    __syncthreads();

    unsigned long long acc[4][4];
#pragma unroll
    for (int i = 0; i < 4; i++)
#pragma unroll
        for (int j = 0; j < 4; j++) acc[i][j] = 0ull;

    const unsigned long long* s_w2 = (const unsigned long long*)s_w;
#pragma unroll 4
    for (int k = 0; k < KIN; k++) {
        float4 xq = *(const float4*)(s_x + k * XS + 4 * rg);
        unsigned long long a0 = pk_dup(xq.x), a1 = pk_dup(xq.y),
                           a2 = pk_dup(xq.z), a3 = pk_dup(xq.w);
        ulonglong2 b01 = *(const ulonglong2*)(s_w2 + ((k * OUT + cg * 8) >> 1));
        ulonglong2 b23 = *(const ulonglong2*)(s_w2 + ((k * OUT + cg * 8) >> 1) + 2);
        fma2(acc[0][0], a0, b01.x); fma2(acc[0][1], a0, b01.y);
        fma2(acc[0][2], a0, b23.x); fma2(acc[0][3], a0, b23.y);
        fma2(acc[1][0], a1, b01.x); fma2(acc[1][1], a1, b01.y);
        fma2(acc[1][2], a1, b23.x); fma2(acc[1][3], a1, b23.y);
        fma2(acc[2][0], a2, b01.x); fma2(acc[2][1], a2, b01.y);
        fma2(acc[2][2], a2, b23.x); fma2(acc[2][3], a2, b23.y);
        fma2(acc[3][0], a3, b01.x); fma2(acc[3][1], a3, b01.y);
        fma2(acc[3][2], a3, b23.x); fma2(acc[3][3], a3, b23.y);
    }

    float bl[8];
#pragma unroll
    for (int j = 0; j < 8; j++) bl[j] = bias[cg * 8 + j];
    float psum[8], psq[8];
#pragma unroll
    for (int j = 0; j < 8; j++) { psum[j] = 0.f; psq[j] = 0.f; }

#pragma unroll
    for (int r = 0; r < 4; r++) {
        float yv[8];
#pragma unroll
        for (int jp = 0; jp < 4; jp++) unpk(acc[r][jp], yv[2*jp], yv[2*jp+1]);
#pragma unroll
        for (int j = 0; j < 8; j++) {
            yv[j] = yv[j] + bl[j];
            psum[j] += yv[j];
            psq[j]  = fmaf(yv[j], yv[j], psq[j]);
        }
        size_t row = row0 + 4 * rg + r;
        float4* dst = (float4*)&Y[row * OUT + cg * 8];
        dst[0] = make_float4(yv[0], yv[1], yv[2], yv[3]);
        dst[1] = make_float4(yv[4], yv[5], yv[6], yv[7]);
    }
#pragma unroll
    for (int j = 0; j < 8; j++) {
#pragma unroll
        for (int off = 16; off; off >>= 1) {
            psum[j] += __shfl_down_sync(0xffffffffu, psum[j], off);
            psq[j]  += __shfl_down_sync(0xffffffffu, psq[j],  off);
        }
    }
    if ((tid & 31) == 0) {
#pragma unroll
        for (int j = 0; j < 8; j++) {
            atomicAdd(&sums[cg * 8 + j],       (double)psum[j]);
            atomicAdd(&sums[OUT + cg * 8 + j], (double)psq[j]);
        }
    }
}

// ==== GEMM layer 2: col-split (grid.y=2), gemm01 geometry, stats+max/min ===
// Each CTA: 128 rows x 64 cols (cols [ch*64, ch*64+64)). Per-element k-chain
// and col-pair packing identical to before -> bit-exact y.
__global__ __launch_bounds__(256) void gemm2_kernel(const float* __restrict__ W,
                                                    const float* __restrict__ bias) {
    constexpr int KIN = 64, OUTF = 128, COLS = 64, RPB = 128, XS = RPB + 4;

    extern __shared__ float sm[];
    float* s_x = sm;                 // [64][132]
    float* s_w = sm + KIN * XS;      // [64][64]  (this CTA's col half)
    double* sums = g_sums + 256;

    const int tid = threadIdx.x;
    const int cg = tid >> 5, rg = tid & 31;      // 8 col-groups x 8 cols, 32 row-groups x 4 rows
    const int ch = blockIdx.y;                   // col half
    const int col0 = ch * COLS;
    const size_t row0 = (size_t)blockIdx.x * RPB;

    for (int i = tid; i < KIN * COLS; i += 256) {
        int k = i / COLS, c = i - k * COLS;
        s_w[k * COLS + c] = W[(col0 + c) * KIN + k];
    }
    for (int i = tid; i < RPB * KIN; i += 256) {
        int r = i / KIN, k = i - r * KIN;
        float v = g_y1[(row0 + r) * KIN + k];
        v = fmaxf(fmaf(v, __ldg(&g_scale[64 + k]), __ldg(&g_shift[64 + k])), 0.f);
        s_x[k * XS + r] = v;
    }
    __syncthreads();

    unsigned long long acc[4][4];
#pragma unroll
    for (int i = 0; i < 4; i++)
#pragma unroll
        for (int j = 0; j < 4; j++) acc[i][j] = 0ull;

    const unsigned long long* s_w2 = (const unsigned long long*)s_w;
#pragma unroll 4
    for (int k = 0; k < KIN; k++) {
        float4 xq = *(const float4*)(s_x + k * XS + 4 * rg);
        unsigned long long a0 = pk_dup(xq.x), a1 = pk_dup(xq.y),
                           a2 = pk_dup(xq.z), a3 = pk_dup(xq.w);
        ulonglong2 b01 = *(const ulonglong2*)(s_w2 + ((k * COLS + cg * 8) >> 1));
        ulonglong2 b23 = *(const ulonglong2*)(s_w2 + ((k * COLS + cg * 8) >> 1) + 2);
        fma2(acc[0][0], a0, b01.x); fma2(acc[0][1], a0, b01.y);
        fma2(acc[0][2], a0, b23.x); fma2(acc[0][3], a0, b23.y);
        fma2(acc[1][0], a1, b01.x); fma2(acc[1][1], a1, b01.y);
        fma2(acc[1][2], a1, b23.x); fma2(acc[1][3], a1, b23.y);
        fma2(acc[2][0], a2, b01.x); fma2(acc[2][1], a2, b01.y);
        fma2(acc[2][2], a2, b23.x); fma2(acc[2][3], a2, b23.y);
        fma2(acc[3][0], a3, b01.x); fma2(acc[3][1], a3, b01.y);
        fma2(acc[3][2], a3, b23.x); fma2(acc[3][3], a3, b23.y);
    }

    float bl[8];
#pragma unroll
    for (int j = 0; j < 8; j++) bl[j] = bias[col0 + cg * 8 + j];
    float psum[8], psq[8], tmax[8], tmin[8];
#pragma unroll
    for (int j = 0; j < 8; j++) {
        psum[j] = 0.f; psq[j] = 0.f; tmax[j] = -1e30f; tmin[j] = 1e30f;
    }

#pragma unroll
    for (int r = 0; r < 4; r++) {
        float yv[8];
#pragma unroll
        for (int jp = 0; jp < 4; jp++) unpk(acc[r][jp], yv[2*jp], yv[2*jp+1]);
#pragma unroll
        for (int j = 0; j < 8; j++) {
            yv[j] = yv[j] + bl[j];
            psum[j] += yv[j];
            psq[j]  = fmaf(yv[j], yv[j], psq[j]);
            tmax[j] = fmaxf(tmax[j], yv[j]);
            tmin[j] = fminf(tmin[j], yv[j]);
        }
    }
    // stats over all 128 rows (full warp shares this col-group)
#pragma unroll
    for (int j = 0; j < 8; j++) {
#pragma unroll
        for (int off = 16; off; off >>= 1) {
            psum[j] += __shfl_down_sync(0xffffffffu, psum[j], off);
            psq[j]  += __shfl_down_sync(0xffffffffu, psq[j],  off);
        }
    }
    if ((tid & 31) == 0) {
        int gc = col0 + cg * 8;
#pragma unroll
        for (int j = 0; j < 8; j++) {
            atomicAdd(&sums[gc + j],        (double)psum[j]);
            atomicAdd(&sums[OUTF + gc + j], (double)psq[j]);
        }
    }
    // per-sample (32 rows = 8 consecutive lanes) max/min
#pragma unroll
    for (int j = 0; j < 8; j++) {
#pragma unroll
        for (int off = 4; off; off >>= 1) {
            tmax[j] = fmaxf(tmax[j], __shfl_down_sync(0xffffffffu, tmax[j], off, 8));
            tmin[j] = fminf(tmin[j], __shfl_down_sync(0xffffffffu, tmin[j], off, 8));
        }
    }
    if ((rg & 7) == 0) {
        size_t samp = row0 / 32 + (rg >> 3);
        int gc = col0 + cg * 8;
        float* pma = &g_ymax[samp * 128 + gc];
        float* pmi = &g_ymin[samp * 128 + gc];
        ((float4*)pma)[0] = make_float4(tmax[0], tmax[1], tmax[2], tmax[3]);
        ((float4*)pma)[1] = make_float4(tmax[4], tmax[5], tmax[6], tmax[7]);
        ((float4*)pmi)[0] = make_float4(tmin[0], tmin[1], tmin[2], tmin[3]);
        ((float4*)pmi)[1] = make_float4(tmin[4], tmin[5], tmin[6], tmin[7]);
    }
}

__global__ void finalize_kernel(const float* __restrict__ g, const float* __restrict__ be,
                                int O, int soff, int scoff) {
    int c = threadIdx.x;
    if (c >= O) return;
    double n = (double)NROWS;
    double mean = g_sums[soff + c] / n;
    double var  = g_sums[soff + O + c] / n - mean * mean;
    double sc   = (double)g[c] * rsqrt(var + 1e-5);
    g_scale[scoff + c] = (float)sc;
    g_shift[scoff + c] = (float)((double)be[c] - mean * sc);
}

// maxpool via pre-reduced max/min: relu(fma(y,sc,sh)) monotone in y for
// fixed sign(sc) -> exact.
__global__ __launch_bounds__(128) void maxpool_kernel(float* __restrict__ out) {
    int bs = blockIdx.x, c = threadIdx.x;
    float sc = g_scale[128 + c], sh = g_shift[128 + c];
    float v = (sc >= 0.f) ? g_ymax[(size_t)bs * 128 + c] : g_ymin[(size_t)bs * 128 + c];
    out[OUT_OFF + (size_t)bs * 128 + c] = fmaxf(fmaf(v, sc, sh), 0.f);
}

// ============================ launcher ====================================
extern "C" void kernel_launch(void* const* d_in, const int* in_sizes, int n_in,
                              void* d_out, int out_size) {
    const float* data = (const float*)d_in[0];
    const float* feat = (const float*)d_in[1];
    const int*   initf = (const int*)d_in[2];
    const float* W0 = (const float*)d_in[3];  const float* b0 = (const float*)d_in[4];
    const float* g0 = (const float*)d_in[5];  const float* be0 = (const float*)d_in[6];
    const float* W1 = (const float*)d_in[7];  const float* b1 = (const float*)d_in[8];
    const float* g1 = (const float*)d_in[9];  const float* be1 = (const float*)d_in[10];
    const float* W2 = (const float*)d_in[11]; const float* b2 = (const float*)d_in[12];
    const float* g2 = (const float*)d_in[13]; const float* be2 = (const float*)d_in[14];
    float* out = (float*)d_out;

    const int smf = NPTS * 3 * 4 + 128 * 4;          // fps: 49664
    const int smb = 58368 + 32;                      // build
    const int sm0 = (68*132 + 68*64) * 4;            // 53312
    const int sm1 = (64*132 + 64*64) * 4;            // 50176
    const int sm2 = (64*132 + 64*64) * 4;            // 50176
    cudaFuncSetAttribute((const void*)fps_kernel,       cudaFuncAttributeMaxDynamicSharedMemorySize, smf);
    cudaFuncSetAttribute((const void*)build_kernel,     cudaFuncAttributeMaxDynamicSharedMemorySize, smb);
    cudaFuncSetAttribute((const void*)gemm01_kernel<0>, cudaFuncAttributeMaxDynamicSharedMemorySize, sm0);
    cudaFuncSetAttribute((const void*)gemm01_kernel<1>, cudaFuncAttributeMaxDynamicSharedMemorySize, sm1);
    cudaFuncSetAttribute((const void*)gemm2_kernel,     cudaFuncAttributeMaxDynamicSharedMemorySize, sm2);

    zero_stats_kernel<<<1, 512>>>();
    fps_kernel<<<NBATCH, 1024, smf>>>(data, initf, out);
    probe_kernel<<<1, 32>>>();   // shifts ncu capture window onto build_kernel
    build_kernel<<<NBATCH * NSAMP, 256, smb>>>(data, feat);
    gemm01_kernel<0><<<NROWS / 128, 256, sm0>>>(W0, b0);
    finalize_kernel<<<1, 128>>>(g0, be0, 64, 0, 0);
    gemm01_kernel<1><<<NROWS / 128, 256, sm1>>>(W1, b1);
    finalize_kernel<<<1, 128>>>(g1, be1, 64, 128, 64);
    gemm2_kernel<<<dim3(NROWS / 128, 2), 256, sm2>>>(W2, b2);
    finalize_kernel<<<1, 128>>>(g2, be2, 128, 256, 128);
    maxpool_kernel<<<NBATCH * NSAMP, 128>>>(out);
}

// round 12
// speedup vs baseline: 1.7665x; 1.0499x over previous
#include <cuda_runtime.h>
#include <math.h>

#define NPTS   4096
#define NBATCH 16
#define NSAMP  1024
#define NK     32
#define NROWS  (NBATCH*NSAMP*NK)      /* 524288 */
#define NSAMPT (NBATCH*NSAMP)         /* 16384  */
#define OUT_OFF (NBATCH*NSAMP*3)      /* 49152  */

// ---------------- device scratch (no allocations allowed) ----------------
__device__ float  g_centroids[NBATCH*NSAMP*3];
__device__ float  g_x0[(size_t)NROWS*68];
__device__ float  g_y0[(size_t)NROWS*64];
__device__ float  g_y1[(size_t)NROWS*64];
__device__ float  g_ymax[(size_t)NSAMPT*128];
__device__ float  g_ymin[(size_t)NSAMPT*128];
__device__ double g_sums[512];
__device__ float  g_scale[256];
__device__ float  g_shift[256];

__global__ void zero_stats_kernel() {
    int t = threadIdx.x;
    if (t < 512) g_sums[t] = 0.0;
}

// no-op: keeps the fixed-position ncu capture on build_kernel
__global__ void probe_kernel() {}

// ---------------- packed f32x2 helpers (exact RN f32 math) ---------------
__device__ __forceinline__ unsigned long long pk_dup(float x) {
    unsigned long long r; unsigned u = __float_as_uint(x);
    asm("mov.b64 %0, {%1, %1};" : "=l"(r) : "r"(u));
    return r;
}
__device__ __forceinline__ void fma2(unsigned long long& d, unsigned long long a,
                                     unsigned long long b) {
    asm("fma.rn.f32x2 %0, %1, %2, %0;" : "+l"(d) : "l"(a), "l"(b));
}
__device__ __forceinline__ void unpk(unsigned long long v, float& lo, float& hi) {
    unsigned a, b;
    asm("mov.b64 {%0, %1}, %2;" : "=r"(a), "=r"(b) : "l"(v));
    lo = __uint_as_float(a); hi = __uint_as_float(b);
}

// ============================ FPS (REDUX version, banked win) ==============
__global__ __launch_bounds__(1024) void fps_kernel(const float* __restrict__ data,
                                                   const int* __restrict__ initf,
                                                   float* __restrict__ out) {
    extern __shared__ float fsm[];
    float* s_px = fsm;
    float* s_py = fsm + NPTS;
    float* s_pz = fsm + 2*NPTS;
    unsigned* s_rd = (unsigned*)(fsm + 3*NPTS);   // 64 (double-buffered)
    unsigned* s_ri = s_rd + 64;

    const int b = blockIdx.x, tid = threadIdx.x;
    const int lane = tid & 31, wid = tid >> 5;
    const float* db = data + (size_t)b * NPTS * 3;

    float px[4], py[4], pz[4], dist[4];
#pragma unroll
    for (int i = 0; i < 4; i++) {
        int n = tid + i * 1024;
        float x = db[n*3+0], y = db[n*3+1], z = db[n*3+2];
        px[i] = x; py[i] = y; pz[i] = z;
        s_px[n] = x; s_py[n] = y; s_pz[n] = z;
        dist[i] = 1e10f;
    }
    int far = __ldg(initf + b);
    __syncthreads();

    for (int s = 0; s < NSAMP; s++) {
        float cx = s_px[far], cy = s_py[far], cz = s_pz[far];
        if (tid == 0) {
            int o = (b*NSAMP + s) * 3;
            out[o] = cx; out[o+1] = cy; out[o+2] = cz;
            g_centroids[o] = cx; g_centroids[o+1] = cy; g_centroids[o+2] = cz;
        }
        unsigned long long best = 0ull;
#pragma unroll
        for (int i = 0; i < 4; i++) {
            float dx = px[i]-cx, dy = py[i]-cy, dz = pz[i]-cz;
            float d = dx*dx + dy*dy + dz*dz;
            dist[i] = fminf(dist[i], d);
            unsigned long long key =
                ((unsigned long long)__float_as_uint(dist[i]) << 32) |
                (unsigned)(4095 - (tid + i*1024));
            best = best > key ? best : key;
        }
        unsigned d32 = (unsigned)(best >> 32);
        unsigned i32 = (unsigned)best;
        unsigned wd = __reduce_max_sync(0xffffffffu, d32);
        unsigned ci = (d32 == wd) ? i32 : 0u;
        unsigned wi = __reduce_max_sync(0xffffffffu, ci);
        int par = (s & 1) * 32;
        if (lane == 0) { s_rd[par + wid] = wd; s_ri[par + wid] = wi; }
        __syncthreads();
        unsigned dv = s_rd[par + lane], iv = s_ri[par + lane];
        unsigned gd = __reduce_max_sync(0xffffffffu, dv);
        unsigned c2 = (dv == gd) ? iv : 0u;
        unsigned gi = __reduce_max_sync(0xffffffffu, c2);
        far = 4095 - (int)gi;
    }
}

// ==================== stage 2+3: top64 -> top32 -> x0 rows ================
struct Stage3 {
    float px[64], py[64], pz[64];
    unsigned long long sk[64];
    float snx[32], sny[32], snz[32], zw[32];
    int   tk[32];
};

__device__ __forceinline__ unsigned ord_f32(float v) {
    unsigned u = __float_as_uint(v);
    return (u & 0x80000000u) ? ~u : (u | 0x80000000u);
}

// Bit-exact replication of the reference square-dist (verified passing):
__device__ __forceinline__ float sqdist_ref(float cx, float cy, float cz, float an2,
                                            float x, float y, float z) {
    float e   = __fmaf_rn(cz, z, __fmaf_rn(cy, y, __fmul_rn(cx, x)));
    float bn2 = __fadd_rn(__fadd_rn(__fmul_rn(x, x), __fmul_rn(y, y)), __fmul_rn(z, z));
    return __fadd_rn(__fadd_rn(__fmul_rn(-2.f, e), an2), bn2);
}

// 42KB smem (was 58.4KB): 5 CTAs/SM instead of 3. Same 12-bit bins, same
// threshold semantics (u>>20 == old key>>52), same candidate set & sort keys.
__global__ __launch_bounds__(256) void build_kernel(const float* __restrict__ data,
                                                    const float* __restrict__ feat) {
    extern __shared__ char bsm[];
    unsigned*           s_u    = (unsigned*)bsm;                      // 4096*4 = 16384
    unsigned int*       s_hist = (unsigned int*)(bsm + 16384);        // 4096*4 = 16384
    unsigned long long* s_cand = (unsigned long long*)(bsm + 32768);  // 1024*8 = 8192
    int*                s_tot  = (int*)(bsm + 40960);                 // 256*4  = 1024
    int*                s_ctl  = (int*)(bsm + 41984);                 // [0]=T [1]=m

    const int tid = threadIdx.x;
    const int b = blockIdx.x >> 10, s = blockIdx.x & 1023;
    const float* db = data + (size_t)b * NPTS * 3;
    const int co = (b*NSAMP + s) * 3;
    const float cx = g_centroids[co], cy = g_centroids[co+1], cz = g_centroids[co+2];
    const float an2 = __fadd_rn(__fadd_rn(__fmul_rn(cx, cx), __fmul_rn(cy, cy)),
                                __fmul_rn(cz, cz));

    {
        uint4* hz = (uint4*)s_hist;
        for (int i = tid; i < 1024; i += 256) hz[i] = make_uint4(0u, 0u, 0u, 0u);
    }
    if (tid == 0) s_ctl[1] = 0;
    __syncthreads();

    // pass 1: compute 32-bit ordered keys once, cache, histogram top 12 bits
    for (int i = 0; i < 16; i++) {
        int n = tid + i * 256;
        float x = db[n*3], y = db[n*3+1], z = db[n*3+2];
        float v = sqdist_ref(cx, cy, cz, an2, x, y, z);
        unsigned u = ord_f32(v);
        s_u[n] = u;
        atomicAdd(&s_hist[u >> 20], 1u);
    }
    __syncthreads();

    // chunk totals (16 bins per thread), then single-warp suffix scan
    {
        unsigned tot = 0;
        for (int j = 0; j < 16; j++) tot += s_hist[tid*16 + j];
        s_tot[tid] = (int)tot;
    }
    __syncthreads();
    if (tid < 32) {
        int base = tid * 8;
        int t[8]; int S = 0;
#pragma unroll
        for (int j = 0; j < 8; j++) { t[j] = s_tot[base + j]; S += t[j]; }
        int suf = S;   // inclusive suffix over lanes
#pragma unroll
        for (int off = 1; off < 32; off <<= 1) {
            int v = __shfl_down_sync(0xffffffffu, suf, off);
            if (tid + off < 32) suf += v;
        }
        int run = suf - S;   // sum of chunks above this lane's range
#pragma unroll
        for (int j = 7; j >= 0; j--) {
            s_tot[base + j] = run;   // cum[c] = totals of chunks > c
            run += t[j];
        }
    }
    __syncthreads();
    {
        unsigned cum = (unsigned)s_tot[tid];
        for (int j = 15; j >= 0; j--) {
            unsigned h = s_hist[tid*16 + j];
            if (cum < 64u && cum + h >= 64u) s_ctl[0] = tid*16 + j;   // unique crossing
            cum += h;
        }
    }
    __syncthreads();
    const unsigned T = (unsigned)s_ctl[0];

    // pass 2: pure smem scan of cached keys, push candidates with bin >= T
    for (int i = 0; i < 16; i++) {
        int n = tid + i * 256;
        unsigned u = s_u[n];
        if ((u >> 20) >= T) {
            int slot = atomicAdd(&s_ctl[1], 1);
            if (slot < 1024)
                s_cand[slot] = ((unsigned long long)u << 32) | (unsigned)(4095 - n);
        }
    }
    __syncthreads();
    int M = s_ctl[1]; if (M > 1024) M = 1024;
    int P = 64; while (P < M) P <<= 1;
    for (int i = M + tid; i < P; i += 256) s_cand[i] = 0ull;

    // bitonic sort descending
    for (int k = 2; k <= P; k <<= 1)
        for (int j = k >> 1; j > 0; j >>= 1) {
            __syncthreads();
            for (int i = tid; i < P; i += 256) {
                int ix = i ^ j;
                if (ix > i) {
                    unsigned long long a = s_cand[i], c = s_cand[ix];
                    if (((i & k) == 0) ? (a < c) : (a > c)) { s_cand[i] = c; s_cand[ix] = a; }
                }
            }
        }
    __syncthreads();

    Stage3* st = (Stage3*)s_hist;   // alias dead histogram
    if (tid < 64) {
        int id = 4095 - (int)(unsigned)(s_cand[tid] & 0xFFFFFFFFull);
        st->px[tid] = db[id*3]; st->py[tid] = db[id*3+1]; st->pz[tid] = db[id*3+2];
    }
    __syncthreads();
    if (tid < 64) {
        float sc = fabsf(st->pz[tid] - st->pz[(tid + 63) & 63]);   // roll(+1)
        st->sk[tid] = ((unsigned long long)__float_as_uint(sc) << 32) | (unsigned)(63 - tid);
    }
    for (int k = 2; k <= 64; k <<= 1)
        for (int j = k >> 1; j > 0; j >>= 1) {
            __syncthreads();
            if (tid < 64) {
                int i = tid, ix = i ^ j;
                if (ix > i) {
                    unsigned long long a = st->sk[i], c = st->sk[ix];
                    if (((i & k) == 0) ? (a < c) : (a > c)) { st->sk[i] = c; st->sk[ix] = a; }
                }
            }
        }
    __syncthreads();

    if (tid < 32) {
        int j = 63 - (int)(unsigned)(st->sk[tid] & 63ull);   // tki
        float sx = st->px[j] - cx, sy = st->py[j] - cy, sz = st->pz[j] - cz;
        float w = fabsf(st->pz[j] - cz);
        float m = w;
#pragma unroll
        for (int off = 16; off; off >>= 1) m = fmaxf(m, __shfl_xor_sync(0xffffffffu, m, off));
        float e = expf(w - m);
        float su = e;
#pragma unroll
        for (int off = 16; off; off >>= 1) su += __shfl_xor_sync(0xffffffffu, su, off);
        st->snx[tid] = sx; st->sny[tid] = sy; st->snz[tid] = sz;
        st->zw[tid] = e / su;
        st->tk[tid] = j;
    }
    __syncthreads();

    size_t R0 = (size_t)(b*NSAMP + s) * NK;
    for (int e = tid; e < NK * 68; e += 256) {
        int k = e / 68, c = e - k * 68;
        float val;
        if (c < 3)        val = (c == 0 ? st->snx[k] : (c == 1 ? st->sny[k] : st->snz[k])) * st->zw[k];
        else if (c < 67)  val = feat[((size_t)b*NPTS + st->tk[k]) * 64 + (c - 3)] * st->zw[k];
        else              val = 0.f;
        g_x0[(R0 + k) * 68 + c] = val;
    }
}

// ==================== GEMM layers 0/1 (round-5 verbatim, 219us) ===========
template<int LAYER>
__global__ __launch_bounds__(256) void gemm01_kernel(const float* __restrict__ W,
                                                     const float* __restrict__ bias) {
    constexpr int KIN   = (LAYER == 0) ? 68 : 64;
    constexpr int KREAL = (LAYER == 0) ? 67 : 64;
    constexpr int OUT   = 64;
    constexpr int RPB   = 128;
    constexpr int XS    = RPB + 4;

    extern __shared__ float sm[];
    float* s_x = sm;                 // [KIN][XS]
    float* s_w = sm + KIN * XS;      // [KIN][OUT]

    const float* X = (LAYER == 0) ? g_x0 : g_y0;
    float*       Y = (LAYER == 0) ? g_y0 : g_y1;
    double* sums = g_sums + ((LAYER == 0) ? 0 : 128);

    const int tid = threadIdx.x;
    const int cg = tid >> 5, rg = tid & 31;
    const size_t row0 = (size_t)blockIdx.x * RPB;

    for (int i = tid; i < KIN * OUT; i += 256) {
        int k = i / OUT, c = i - k * OUT;
        s_w[k * OUT + c] = (k < KREAL) ? W[c * KREAL + k] : 0.f;
    }
    for (int i = tid; i < RPB * KIN; i += 256) {
        int r = i / KIN, k = i - r * KIN;
        float v = X[(row0 + r) * KIN + k];
        if (LAYER > 0)
            v = fmaxf(fmaf(v, __ldg(&g_scale[k]), __ldg(&g_shift[k])), 0.f);
        s_x[k * XS + r] = v;
    }
    __syncthreads();

    unsigned long long acc[4][4];
#pragma unroll
    for (int i = 0; i < 4; i++)
#pragma unroll
        for (int j = 0; j < 4; j++) acc[i][j] = 0ull;

    const unsigned long long* s_w2 = (const unsigned long long*)s_w;
#pragma unroll 4
    for (int k = 0; k < KIN; k++) {
        float4 xq = *(const float4*)(s_x + k * XS + 4 * rg);
        unsigned long long a0 = pk_dup(xq.x), a1 = pk_dup(xq.y),
                           a2 = pk_dup(xq.z), a3 = pk_dup(xq.w);
        ulonglong2 b01 = *(const ulonglong2*)(s_w2 + ((k * OUT + cg * 8) >> 1));
        ulonglong2 b23 = *(const ulonglong2*)(s_w2 + ((k * OUT + cg * 8) >> 1) + 2);
        fma2(acc[0][0], a0, b01.x); fma2(acc[0][1], a0, b01.y);
        fma2(acc[0][2], a0, b23.x); fma2(acc[0][3], a0, b23.y);
        fma2(acc[1][0], a1, b01.x); fma2(acc[1][1], a1, b01.y);
        fma2(acc[1][2], a1, b23.x); fma2(acc[1][3], a1, b23.y);
        fma2(acc[2][0], a2, b01.x); fma2(acc[2][1], a2, b01.y);
        fma2(acc[2][2], a2, b23.x); fma2(acc[2][3], a2, b23.y);
        fma2(acc[3][0], a3, b01.x); fma2(acc[3][1], a3, b01.y);
        fma2(acc[3][2], a3, b23.x); fma2(acc[3][3], a3, b23.y);
    }

    float bl[8];
#pragma unroll
    for (int j = 0; j < 8; j++) bl[j] = bias[cg * 8 + j];
    float psum[8], psq[8];
#pragma unroll
    for (int j = 0; j < 8; j++) { psum[j] = 0.f; psq[j] = 0.f; }

#pragma unroll
    for (int r = 0; r < 4; r++) {
        float yv[8];
#pragma unroll
        for (int jp = 0; jp < 4; jp++) unpk(acc[r][jp], yv[2*jp], yv[2*jp+1]);
#pragma unroll
        for (int j = 0; j < 8; j++) {
            yv[j] = yv[j] + bl[j];
            psum[j] += yv[j];
            psq[j]  = fmaf(yv[j], yv[j], psq[j]);
        }
        size_t row = row0 + 4 * rg + r;
        float4* dst = (float4*)&Y[row * OUT + cg * 8];
        dst[0] = make_float4(yv[0], yv[1], yv[2], yv[3]);
        dst[1] = make_float4(yv[4], yv[5], yv[6], yv[7]);
    }
#pragma unroll
    for (int j = 0; j < 8; j++) {
#pragma unroll
        for (int off = 16; off; off >>= 1) {
            psum[j] += __shfl_down_sync(0xffffffffu, psum[j], off);
            psq[j]  += __shfl_down_sync(0xffffffffu, psq[j],  off);
        }
    }
    if ((tid & 31) == 0) {
#pragma unroll
        for (int j = 0; j < 8; j++) {
            atomicAdd(&sums[cg * 8 + j],       (double)psum[j]);
            atomicAdd(&sums[OUT + cg * 8 + j], (double)psq[j]);
        }
    }
}

// ==== GEMM layer 2: col-split (grid.y=2), gemm01 geometry, stats+max/min ===
__global__ __launch_bounds__(256) void gemm2_kernel(const float* __restrict__ W,
                                                    const float* __restrict__ bias) {
    constexpr int KIN = 64, OUTF = 128, COLS = 64, RPB = 128, XS = RPB + 4;

    extern __shared__ float sm[];
    float* s_x = sm;                 // [64][132]
    float* s_w = sm + KIN * XS;      // [64][64]  (this CTA's col half)
    double* sums = g_sums + 256;

    const int tid = threadIdx.x;
    const int cg = tid >> 5, rg = tid & 31;
    const int ch = blockIdx.y;
    const int col0 = ch * COLS;
    const size_t row0 = (size_t)blockIdx.x * RPB;

    for (int i = tid; i < KIN * COLS; i += 256) {
        int k = i / COLS, c = i - k * COLS;
        s_w[k * COLS + c] = W[(col0 + c) * KIN + k];
    }
    for (int i = tid; i < RPB * KIN; i += 256) {
        int r = i / KIN, k = i - r * KIN;
        float v = g_y1[(row0 + r) * KIN + k];
        v = fmaxf(fmaf(v, __ldg(&g_scale[64 + k]), __ldg(&g_shift[64 + k])), 0.f);
        s_x[k * XS + r] = v;
    }
    __syncthreads();

    unsigned long long acc[4][4];
#pragma unroll
    for (int i = 0; i < 4; i++)
#pragma unroll
        for (int j = 0; j < 4; j++) acc[i][j] = 0ull;

    const unsigned long long* s_w2 = (const unsigned long long*)s_w;
#pragma unroll 4
    for (int k = 0; k < KIN; k++) {
        float4 xq = *(const float4*)(s_x + k * XS + 4 * rg);
        unsigned long long a0 = pk_dup(xq.x), a1 = pk_dup(xq.y),
                           a2 = pk_dup(xq.z), a3 = pk_dup(xq.w);
        ulonglong2 b01 = *(const ulonglong2*)(s_w2 + ((k * COLS + cg * 8) >> 1));
        ulonglong2 b23 = *(const ulonglong2*)(s_w2 + ((k * COLS + cg * 8) >> 1) + 2);
        fma2(acc[0][0], a0, b01.x); fma2(acc[0][1], a0, b01.y);
        fma2(acc[0][2], a0, b23.x); fma2(acc[0][3], a0, b23.y);
        fma2(acc[1][0], a1, b01.x); fma2(acc[1][1], a1, b01.y);
        fma2(acc[1][2], a1, b23.x); fma2(acc[1][3], a1, b23.y);
        fma2(acc[2][0], a2, b01.x); fma2(acc[2][1], a2, b01.y);
        fma2(acc[2][2], a2, b23.x); fma2(acc[2][3], a2, b23.y);
        fma2(acc[3][0], a3, b01.x); fma2(acc[3][1], a3, b01.y);
        fma2(acc[3][2], a3, b23.x); fma2(acc[3][3], a3, b23.y);
    }

    float bl[8];
#pragma unroll
    for (int j = 0; j < 8; j++) bl[j] = bias[col0 + cg * 8 + j];
    float psum[8], psq[8], tmax[8], tmin[8];
#pragma unroll
    for (int j = 0; j < 8; j++) {
        psum[j] = 0.f; psq[j] = 0.f; tmax[j] = -1e30f; tmin[j] = 1e30f;
    }

#pragma unroll
    for (int r = 0; r < 4; r++) {
        float yv[8];
#pragma unroll
        for (int jp = 0; jp < 4; jp++) unpk(acc[r][jp], yv[2*jp], yv[2*jp+1]);
#pragma unroll
        for (int j = 0; j < 8; j++) {
            yv[j] = yv[j] + bl[j];
            psum[j] += yv[j];
            psq[j]  = fmaf(yv[j], yv[j], psq[j]);
            tmax[j] = fmaxf(tmax[j], yv[j]);
            tmin[j] = fminf(tmin[j], yv[j]);
        }
    }
#pragma unroll
    for (int j = 0; j < 8; j++) {
#pragma unroll
        for (int off = 16; off; off >>= 1) {
            psum[j] += __shfl_down_sync(0xffffffffu, psum[j], off);
            psq[j]  += __shfl_down_sync(0xffffffffu, psq[j],  off);
        }
    }
    if ((tid & 31) == 0) {
        int gc = col0 + cg * 8;
#pragma unroll
        for (int j = 0; j < 8; j++) {
            atomicAdd(&sums[gc + j],        (double)psum[j]);
            atomicAdd(&sums[OUTF + gc + j], (double)psq[j]);
        }
    }
#pragma unroll
    for (int j = 0; j < 8; j++) {
#pragma unroll
        for (int off = 4; off; off >>= 1) {
            tmax[j] = fmaxf(tmax[j], __shfl_down_sync(0xffffffffu, tmax[j], off, 8));
            tmin[j] = fminf(tmin[j], __shfl_down_sync(0xffffffffu, tmin[j], off, 8));
        }
    }
    if ((rg & 7) == 0) {
        size_t samp = row0 / 32 + (rg >> 3);
        int gc = col0 + cg * 8;
        float* pma = &g_ymax[samp * 128 + gc];
        float* pmi = &g_ymin[samp * 128 + gc];
        ((float4*)pma)[0] = make_float4(tmax[0], tmax[1], tmax[2], tmax[3]);
        ((float4*)pma)[1] = make_float4(tmax[4], tmax[5], tmax[6], tmax[7]);
        ((float4*)pmi)[0] = make_float4(tmin[0], tmin[1], tmin[2], tmin[3]);
        ((float4*)pmi)[1] = make_float4(tmin[4], tmin[5], tmin[6], tmin[7]);
    }
}

__global__ void finalize_kernel(const float* __restrict__ g, const float* __restrict__ be,
                                int O, int soff, int scoff) {
    int c = threadIdx.x;
    if (c >= O) return;
    double n = (double)NROWS;
    double mean = g_sums[soff + c] / n;
    double var  = g_sums[soff + O + c] / n - mean * mean;
    double sc   = (double)g[c] * rsqrt(var + 1e-5);
    g_scale[scoff + c] = (float)sc;
    g_shift[scoff + c] = (float)((double)be[c] - mean * sc);
}

__global__ __launch_bounds__(128) void maxpool_kernel(float* __restrict__ out) {
    int bs = blockIdx.x, c = threadIdx.x;
    float sc = g_scale[128 + c], sh = g_shift[128 + c];
    float v = (sc >= 0.f) ? g_ymax[(size_t)bs * 128 + c] : g_ymin[(size_t)bs * 128 + c];
    out[OUT_OFF + (size_t)bs * 128 + c] = fmaxf(fmaf(v, sc, sh), 0.f);
}

// ============================ launcher ====================================
extern "C" void kernel_launch(void* const* d_in, const int* in_sizes, int n_in,
                              void* d_out, int out_size) {
    const float* data = (const float*)d_in[0];
    const float* feat = (const float*)d_in[1];
    const int*   initf = (const int*)d_in[2];
    const float* W0 = (const float*)d_in[3];  const float* b0 = (const float*)d_in[4];
    const float* g0 = (const float*)d_in[5];  const float* be0 = (const float*)d_in[6];
    const float* W1 = (const float*)d_in[7];  const float* b1 = (const float*)d_in[8];
    const float* g1 = (const float*)d_in[9];  const float* be1 = (const float*)d_in[10];
    const float* W2 = (const float*)d_in[11]; const float* b2 = (const float*)d_in[12];
    const float* g2 = (const float*)d_in[13]; const float* be2 = (const float*)d_in[14];
    float* out = (float*)d_out;

    const int smf = NPTS * 3 * 4 + 128 * 4;          // fps: 49664
    const int smb = 42048;                           // build (was 58400)
    const int sm0 = (68*132 + 68*64) * 4;            // 53312
    const int sm1 = (64*132 + 64*64) * 4;            // 50176
    const int sm2 = (64*132 + 64*64) * 4;            // 50176
    cudaFuncSetAttribute((const void*)fps_kernel,       cudaFuncAttributeMaxDynamicSharedMemorySize, smf);
    cudaFuncSetAttribute((const void*)build_kernel,     cudaFuncAttributeMaxDynamicSharedMemorySize, smb);
    cudaFuncSetAttribute((const void*)gemm01_kernel<0>, cudaFuncAttributeMaxDynamicSharedMemorySize, sm0);
    cudaFuncSetAttribute((const void*)gemm01_kernel<1>, cudaFuncAttributeMaxDynamicSharedMemorySize, sm1);
    cudaFuncSetAttribute((const void*)gemm2_kernel,     cudaFuncAttributeMaxDynamicSharedMemorySize, sm2);

    zero_stats_kernel<<<1, 512>>>();
    fps_kernel<<<NBATCH, 1024, smf>>>(data, initf, out);
    probe_kernel<<<1, 32>>>();   // keeps ncu capture window on build_kernel
    build_kernel<<<NBATCH * NSAMP, 256, smb>>>(data, feat);
    gemm01_kernel<0><<<NROWS / 128, 256, sm0>>>(W0, b0);
    finalize_kernel<<<1, 128>>>(g0, be0, 64, 0, 0);
    gemm01_kernel<1><<<NROWS / 128, 256, sm1>>>(W1, b1);
    finalize_kernel<<<1, 128>>>(g1, be1, 64, 128, 64);
    gemm2_kernel<<<dim3(NROWS / 128, 2), 256, sm2>>>(W2, b2);
    finalize_kernel<<<1, 128>>>(g2, be2, 128, 256, 128);
    maxpool_kernel<<<NBATCH * NSAMP, 128>>>(out);
}

// round 13
// speedup vs baseline: 1.9018x; 1.0766x over previous
#include <cuda_runtime.h>
#include <math.h>

#define NPTS   4096
#define NBATCH 16
#define NSAMP  1024
#define NK     32
#define NROWS  (NBATCH*NSAMP*NK)      /* 524288 */
#define NSAMPT (NBATCH*NSAMP)         /* 16384  */
#define OUT_OFF (NBATCH*NSAMP*3)      /* 49152  */

// ---------------- device scratch (no allocations allowed) ----------------
__device__ float  g_centroids[NBATCH*NSAMP*3];
__device__ float  g_x0[(size_t)NROWS*68];
__device__ float  g_y0[(size_t)NROWS*64];
__device__ float  g_y1[(size_t)NROWS*64];
__device__ float  g_ymax[(size_t)NSAMPT*128];
__device__ float  g_ymin[(size_t)NSAMPT*128];
__device__ double g_sums[512];
__device__ float  g_scale[256];
__device__ float  g_shift[256];

__global__ void zero_stats_kernel() {
    int t = threadIdx.x;
    if (t < 512) g_sums[t] = 0.0;
}

// no-op: keeps the fixed-position ncu capture on build_kernel
__global__ void probe_kernel() {}

// ---------------- packed f32x2 helpers (exact RN f32 math) ---------------
__device__ __forceinline__ unsigned long long pk_dup(float x) {
    unsigned long long r; unsigned u = __float_as_uint(x);
    asm("mov.b64 %0, {%1, %1};" : "=l"(r) : "r"(u));
    return r;
}
__device__ __forceinline__ void fma2(unsigned long long& d, unsigned long long a,
                                     unsigned long long b) {
    asm("fma.rn.f32x2 %0, %1, %2, %0;" : "+l"(d) : "l"(a), "l"(b));
}
__device__ __forceinline__ void unpk(unsigned long long v, float& lo, float& hi) {
    unsigned a, b;
    asm("mov.b64 {%0, %1}, %2;" : "=r"(a), "=r"(b) : "l"(v));
    lo = __uint_as_float(a); hi = __uint_as_float(b);
}

// ============================ FPS (REDUX version, banked win) ==============
__global__ __launch_bounds__(1024) void fps_kernel(const float* __restrict__ data,
                                                   const int* __restrict__ initf,
                                                   float* __restrict__ out) {
    extern __shared__ float fsm[];
    float* s_px = fsm;
    float* s_py = fsm + NPTS;
    float* s_pz = fsm + 2*NPTS;
    unsigned* s_rd = (unsigned*)(fsm + 3*NPTS);   // 64 (double-buffered)
    unsigned* s_ri = s_rd + 64;

    const int b = blockIdx.x, tid = threadIdx.x;
    const int lane = tid & 31, wid = tid >> 5;
    const float* db = data + (size_t)b * NPTS * 3;

    float px[4], py[4], pz[4], dist[4];
#pragma unroll
    for (int i = 0; i < 4; i++) {
        int n = tid + i * 1024;
        float x = db[n*3+0], y = db[n*3+1], z = db[n*3+2];
        px[i] = x; py[i] = y; pz[i] = z;
        s_px[n] = x; s_py[n] = y; s_pz[n] = z;
        dist[i] = 1e10f;
    }
    int far = __ldg(initf + b);
    __syncthreads();

    for (int s = 0; s < NSAMP; s++) {
        float cx = s_px[far], cy = s_py[far], cz = s_pz[far];
        if (tid == 0) {
            int o = (b*NSAMP + s) * 3;
            out[o] = cx; out[o+1] = cy; out[o+2] = cz;
            g_centroids[o] = cx; g_centroids[o+1] = cy; g_centroids[o+2] = cz;
        }
        unsigned long long best = 0ull;
#pragma unroll
        for (int i = 0; i < 4; i++) {
            float dx = px[i]-cx, dy = py[i]-cy, dz = pz[i]-cz;
            float d = dx*dx + dy*dy + dz*dz;
            dist[i] = fminf(dist[i], d);
            unsigned long long key =
                ((unsigned long long)__float_as_uint(dist[i]) << 32) |
                (unsigned)(4095 - (tid + i*1024));
            best = best > key ? best : key;
        }
        unsigned d32 = (unsigned)(best >> 32);
        unsigned i32 = (unsigned)best;
        unsigned wd = __reduce_max_sync(0xffffffffu, d32);
        unsigned ci = (d32 == wd) ? i32 : 0u;
        unsigned wi = __reduce_max_sync(0xffffffffu, ci);
        int par = (s & 1) * 32;
        if (lane == 0) { s_rd[par + wid] = wd; s_ri[par + wid] = wi; }
        __syncthreads();
        unsigned dv = s_rd[par + lane], iv = s_ri[par + lane];
        unsigned gd = __reduce_max_sync(0xffffffffu, dv);
        unsigned c2 = (dv == gd) ? iv : 0u;
        unsigned gi = __reduce_max_sync(0xffffffffu, c2);
        far = 4095 - (int)gi;
    }
}

// ==================== stage 2+3: top64 -> top32 -> x0 rows ================
struct Stage3 {
    float px[64], py[64], pz[64];
    unsigned long long sk[64];
    float snx[32], sny[32], snz[32], zw[32];
    int   tk[32];
};

__device__ __forceinline__ unsigned ord_f32(float v) {
    unsigned u = __float_as_uint(v);
    return (u & 0x80000000u) ? ~u : (u | 0x80000000u);
}

// Bit-exact replication of the reference square-dist (verified passing):
__device__ __forceinline__ float sqdist_ref(float cx, float cy, float cz, float an2,
                                            float x, float y, float z) {
    float e   = __fmaf_rn(cz, z, __fmaf_rn(cy, y, __fmul_rn(cx, x)));
    float bn2 = __fadd_rn(__fadd_rn(__fmul_rn(x, x), __fmul_rn(y, y)), __fmul_rn(z, z));
    return __fadd_rn(__fadd_rn(__fmul_rn(-2.f, e), an2), bn2);
}

// 512 threads, 33.8KB smem -> 4 CTAs x 512 = 2048 thr/SM (100% occ ceiling).
// 2048 bins (u>>21): coarser superset filter, final sort exact -> same top-64.
__global__ __launch_bounds__(512) void build_kernel(const float* __restrict__ data,
                                                    const float* __restrict__ feat) {
    extern __shared__ char bsm[];
    unsigned*           s_u    = (unsigned*)bsm;                      // 4096*4 = 16384
    unsigned int*       s_hist = (unsigned int*)(bsm + 16384);        // 2048*4 = 8192
    unsigned long long* s_cand = (unsigned long long*)(bsm + 24576);  // 1024*8 = 8192
    int*                s_tot  = (int*)(bsm + 32768);                 // 256*4  = 1024
    int*                s_ctl  = (int*)(bsm + 33792);                 // [0]=T [1]=m

    const int tid = threadIdx.x;
    const int b = blockIdx.x >> 10, s = blockIdx.x & 1023;
    const float* db = data + (size_t)b * NPTS * 3;
    const int co = (b*NSAMP + s) * 3;
    const float cx = g_centroids[co], cy = g_centroids[co+1], cz = g_centroids[co+2];
    const float an2 = __fadd_rn(__fadd_rn(__fmul_rn(cx, cx), __fmul_rn(cy, cy)),
                                __fmul_rn(cz, cz));

    {
        uint4* hz = (uint4*)s_hist;
        for (int i = tid; i < 512; i += 512) hz[i] = make_uint4(0u, 0u, 0u, 0u);
    }
    if (tid == 0) s_ctl[1] = 0;
    __syncthreads();

    // pass 1: compute 32-bit ordered keys once, cache, histogram top 11 bits
    for (int i = 0; i < 8; i++) {
        int n = tid + i * 512;
        float x = db[n*3], y = db[n*3+1], z = db[n*3+2];
        float v = sqdist_ref(cx, cy, cz, an2, x, y, z);
        unsigned u = ord_f32(v);
        s_u[n] = u;
        atomicAdd(&s_hist[u >> 21], 1u);
    }
    __syncthreads();

    // chunk totals (8 bins per thread, 256 chunks), then single-warp suffix scan
    if (tid < 256) {
        unsigned tot = 0;
        for (int j = 0; j < 8; j++) tot += s_hist[tid*8 + j];
        s_tot[tid] = (int)tot;
    }
    __syncthreads();
    if (tid < 32) {
        int base = tid * 8;
        int t[8]; int S = 0;
#pragma unroll
        for (int j = 0; j < 8; j++) { t[j] = s_tot[base + j]; S += t[j]; }
        int suf = S;   // inclusive suffix over lanes
#pragma unroll
        for (int off = 1; off < 32; off <<= 1) {
            int v = __shfl_down_sync(0xffffffffu, suf, off);
            if (tid + off < 32) suf += v;
        }
        int run = suf - S;   // sum of chunks above this lane's range
#pragma unroll
        for (int j = 7; j >= 0; j--) {
            s_tot[base + j] = run;   // cum[c] = totals of chunks > c
            run += t[j];
        }
    }
    __syncthreads();
    if (tid < 256) {
        unsigned cum = (unsigned)s_tot[tid];
        for (int j = 7; j >= 0; j--) {
            unsigned h = s_hist[tid*8 + j];
            if (cum < 64u && cum + h >= 64u) s_ctl[0] = tid*8 + j;   // unique crossing
            cum += h;
        }
    }
    __syncthreads();
    const unsigned T = (unsigned)s_ctl[0];

    // pass 2: pure smem scan of cached keys, push candidates with bin >= T
    for (int i = 0; i < 8; i++) {
        int n = tid + i * 512;
        unsigned u = s_u[n];
        if ((u >> 21) >= T) {
            int slot = atomicAdd(&s_ctl[1], 1);
            if (slot < 1024)
                s_cand[slot] = ((unsigned long long)u << 32) | (unsigned)(4095 - n);
        }
    }
    __syncthreads();
    int M = s_ctl[1]; if (M > 1024) M = 1024;
    int P = 64; while (P < M) P <<= 1;
    for (int i = M + tid; i < P; i += 512) s_cand[i] = 0ull;

    // bitonic sort descending
    for (int k = 2; k <= P; k <<= 1)
        for (int j = k >> 1; j > 0; j >>= 1) {
            __syncthreads();
            for (int i = tid; i < P; i += 512) {
                int ix = i ^ j;
                if (ix > i) {
                    unsigned long long a = s_cand[i], c = s_cand[ix];
                    if (((i & k) == 0) ? (a < c) : (a > c)) { s_cand[i] = c; s_cand[ix] = a; }
                }
            }
        }
    __syncthreads();

    Stage3* st = (Stage3*)s_hist;   // alias dead histogram (8KB >= 1.9KB)
    if (tid < 64) {
        int id = 4095 - (int)(unsigned)(s_cand[tid] & 0xFFFFFFFFull);
        st->px[tid] = db[id*3]; st->py[tid] = db[id*3+1]; st->pz[tid] = db[id*3+2];
    }
    __syncthreads();
    if (tid < 64) {
        float sc = fabsf(st->pz[tid] - st->pz[(tid + 63) & 63]);   // roll(+1)
        st->sk[tid] = ((unsigned long long)__float_as_uint(sc) << 32) | (unsigned)(63 - tid);
    }
    for (int k = 2; k <= 64; k <<= 1)
        for (int j = k >> 1; j > 0; j >>= 1) {
            __syncthreads();
            if (tid < 64) {
                int i = tid, ix = i ^ j;
                if (ix > i) {
                    unsigned long long a = st->sk[i], c = st->sk[ix];
                    if (((i & k) == 0) ? (a < c) : (a > c)) { st->sk[i] = c; st->sk[ix] = a; }
                }
            }
        }
    __syncthreads();

    if (tid < 32) {
        int j = 63 - (int)(unsigned)(st->sk[tid] & 63ull);   // tki
        float sx = st->px[j] - cx, sy = st->py[j] - cy, sz = st->pz[j] - cz;
        float w = fabsf(st->pz[j] - cz);
        float m = w;
#pragma unroll
        for (int off = 16; off; off >>= 1) m = fmaxf(m, __shfl_xor_sync(0xffffffffu, m, off));
        float e = expf(w - m);
        float su = e;
#pragma unroll
        for (int off = 16; off; off >>= 1) su += __shfl_xor_sync(0xffffffffu, su, off);
        st->snx[tid] = sx; st->sny[tid] = sy; st->snz[tid] = sz;
        st->zw[tid] = e / su;
        st->tk[tid] = j;
    }
    __syncthreads();

    size_t R0 = (size_t)(b*NSAMP + s) * NK;
    for (int e = tid; e < NK * 68; e += 512) {
        int k = e / 68, c = e - k * 68;
        float val;
        if (c < 3)        val = (c == 0 ? st->snx[k] : (c == 1 ? st->sny[k] : st->snz[k])) * st->zw[k];
        else if (c < 67)  val = feat[((size_t)b*NPTS + st->tk[k]) * 64 + (c - 3)] * st->zw[k];
        else              val = 0.f;
        g_x0[(R0 + k) * 68 + c] = val;
    }
}

// ==================== GEMM layers 0/1 (round-5 verbatim, 219us) ===========
template<int LAYER>
__global__ __launch_bounds__(256) void gemm01_kernel(const float* __restrict__ W,
                                                     const float* __restrict__ bias) {
    constexpr int KIN   = (LAYER == 0) ? 68 : 64;
    constexpr int KREAL = (LAYER == 0) ? 67 : 64;
    constexpr int OUT   = 64;
    constexpr int RPB   = 128;
    constexpr int XS    = RPB + 4;

    extern __shared__ float sm[];
    float* s_x = sm;                 // [KIN][XS]
    float* s_w = sm + KIN * XS;      // [KIN][OUT]

    const float* X = (LAYER == 0) ? g_x0 : g_y0;
    float*       Y = (LAYER == 0) ? g_y0 : g_y1;
    double* sums = g_sums + ((LAYER == 0) ? 0 : 128);

    const int tid = threadIdx.x;
    const int cg = tid >> 5, rg = tid & 31;
    const size_t row0 = (size_t)blockIdx.x * RPB;

    for (int i = tid; i < KIN * OUT; i += 256) {
        int k = i / OUT, c = i - k * OUT;
        s_w[k * OUT + c] = (k < KREAL) ? W[c * KREAL + k] : 0.f;
    }
    for (int i = tid; i < RPB * KIN; i += 256) {
        int r = i / KIN, k = i - r * KIN;
        float v = X[(row0 + r) * KIN + k];
        if (LAYER > 0)
            v = fmaxf(fmaf(v, __ldg(&g_scale[k]), __ldg(&g_shift[k])), 0.f);
        s_x[k * XS + r] = v;
    }
    __syncthreads();

    unsigned long long acc[4][4];
#pragma unroll
    for (int i = 0; i < 4; i++)
#pragma unroll
        for (int j = 0; j < 4; j++) acc[i][j] = 0ull;

    const unsigned long long* s_w2 = (const unsigned long long*)s_w;
#pragma unroll 4
    for (int k = 0; k < KIN; k++) {
        float4 xq = *(const float4*)(s_x + k * XS + 4 * rg);
        unsigned long long a0 = pk_dup(xq.x), a1 = pk_dup(xq.y),
                           a2 = pk_dup(xq.z), a3 = pk_dup(xq.w);
        ulonglong2 b01 = *(const ulonglong2*)(s_w2 + ((k * OUT + cg * 8) >> 1));
        ulonglong2 b23 = *(const ulonglong2*)(s_w2 + ((k * OUT + cg * 8) >> 1) + 2);
        fma2(acc[0][0], a0, b01.x); fma2(acc[0][1], a0, b01.y);
        fma2(acc[0][2], a0, b23.x); fma2(acc[0][3], a0, b23.y);
        fma2(acc[1][0], a1, b01.x); fma2(acc[1][1], a1, b01.y);
        fma2(acc[1][2], a1, b23.x); fma2(acc[1][3], a1, b23.y);
        fma2(acc[2][0], a2, b01.x); fma2(acc[2][1], a2, b01.y);
        fma2(acc[2][2], a2, b23.x); fma2(acc[2][3], a2, b23.y);
        fma2(acc[3][0], a3, b01.x); fma2(acc[3][1], a3, b01.y);
        fma2(acc[3][2], a3, b23.x); fma2(acc[3][3], a3, b23.y);
    }

    float bl[8];
#pragma unroll
    for (int j = 0; j < 8; j++) bl[j] = bias[cg * 8 + j];
    float psum[8], psq[8];
#pragma unroll
    for (int j = 0; j < 8; j++) { psum[j] = 0.f; psq[j] = 0.f; }

#pragma unroll
    for (int r = 0; r < 4; r++) {
        float yv[8];
#pragma unroll
        for (int jp = 0; jp < 4; jp++) unpk(acc[r][jp], yv[2*jp], yv[2*jp+1]);
#pragma unroll
        for (int j = 0; j < 8; j++) {
            yv[j] = yv[j] + bl[j];
            psum[j] += yv[j];
            psq[j]  = fmaf(yv[j], yv[j], psq[j]);
        }
        size_t row = row0 + 4 * rg + r;
        float4* dst = (float4*)&Y[row * OUT + cg * 8];
        dst[0] = make_float4(yv[0], yv[1], yv[2], yv[3]);
        dst[1] = make_float4(yv[4], yv[5], yv[6], yv[7]);
    }
#pragma unroll
    for (int j = 0; j < 8; j++) {
#pragma unroll
        for (int off = 16; off; off >>= 1) {
            psum[j] += __shfl_down_sync(0xffffffffu, psum[j], off);
            psq[j]  += __shfl_down_sync(0xffffffffu, psq[j],  off);
        }
    }
    if ((tid & 31) == 0) {
#pragma unroll
        for (int j = 0; j < 8; j++) {
            atomicAdd(&sums[cg * 8 + j],       (double)psum[j]);
            atomicAdd(&sums[OUT + cg * 8 + j], (double)psq[j]);
        }
    }
}

// ==== GEMM layer 2: col-split (grid.y=2), gemm01 geometry, stats+max/min ===
__global__ __launch_bounds__(256) void gemm2_kernel(const float* __restrict__ W,
                                                    const float* __restrict__ bias) {
    constexpr int KIN = 64, OUTF = 128, COLS = 64, RPB = 128, XS = RPB + 4;

    extern __shared__ float sm[];
    float* s_x = sm;                 // [64][132]
    float* s_w = sm + KIN * XS;      // [64][64]  (this CTA's col half)
    double* sums = g_sums + 256;

    const int tid = threadIdx.x;
    const int cg = tid >> 5, rg = tid & 31;
    const int ch = blockIdx.y;
    const int col0 = ch * COLS;
    const size_t row0 = (size_t)blockIdx.x * RPB;

    for (int i = tid; i < KIN * COLS; i += 256) {
        int k = i / COLS, c = i - k * COLS;
        s_w[k * COLS + c] = W[(col0 + c) * KIN + k];
    }
    for (int i = tid; i < RPB * KIN; i += 256) {
        int r = i / KIN, k = i - r * KIN;
        float v = g_y1[(row0 + r) * KIN + k];
        v = fmaxf(fmaf(v, __ldg(&g_scale[64 + k]), __ldg(&g_shift[64 + k])), 0.f);
        s_x[k * XS + r] = v;
    }
    __syncthreads();

    unsigned long long acc[4][4];
#pragma unroll
    for (int i = 0; i < 4; i++)
#pragma unroll
        for (int j = 0; j < 4; j++) acc[i][j] = 0ull;

    const unsigned long long* s_w2 = (const unsigned long long*)s_w;
#pragma unroll 4
    for (int k = 0; k < KIN; k++) {
        float4 xq = *(const float4*)(s_x + k * XS + 4 * rg);
        unsigned long long a0 = pk_dup(xq.x), a1 = pk_dup(xq.y),
                           a2 = pk_dup(xq.z), a3 = pk_dup(xq.w);
        ulonglong2 b01 = *(const ulonglong2*)(s_w2 + ((k * COLS + cg * 8) >> 1));
        ulonglong2 b23 = *(const ulonglong2*)(s_w2 + ((k * COLS + cg * 8) >> 1) + 2);
        fma2(acc[0][0], a0, b01.x); fma2(acc[0][1], a0, b01.y);
        fma2(acc[0][2], a0, b23.x); fma2(acc[0][3], a0, b23.y);
        fma2(acc[1][0], a1, b01.x); fma2(acc[1][1], a1, b01.y);
        fma2(acc[1][2], a1, b23.x); fma2(acc[1][3], a1, b23.y);
        fma2(acc[2][0], a2, b01.x); fma2(acc[2][1], a2, b01.y);
        fma2(acc[2][2], a2, b23.x); fma2(acc[2][3], a2, b23.y);
        fma2(acc[3][0], a3, b01.x); fma2(acc[3][1], a3, b01.y);
        fma2(acc[3][2], a3, b23.x); fma2(acc[3][3], a3, b23.y);
    }

    float bl[8];
#pragma unroll
    for (int j = 0; j < 8; j++) bl[j] = bias[col0 + cg * 8 + j];
    float psum[8], psq[8], tmax[8], tmin[8];
#pragma unroll
    for (int j = 0; j < 8; j++) {
        psum[j] = 0.f; psq[j] = 0.f; tmax[j] = -1e30f; tmin[j] = 1e30f;
    }

#pragma unroll
    for (int r = 0; r < 4; r++) {
        float yv[8];
#pragma unroll
        for (int jp = 0; jp < 4; jp++) unpk(acc[r][jp], yv[2*jp], yv[2*jp+1]);
#pragma unroll
        for (int j = 0; j < 8; j++) {
            yv[j] = yv[j] + bl[j];
            psum[j] += yv[j];
            psq[j]  = fmaf(yv[j], yv[j], psq[j]);
            tmax[j] = fmaxf(tmax[j], yv[j]);
            tmin[j] = fminf(tmin[j], yv[j]);
        }
    }
#pragma unroll
    for (int j = 0; j < 8; j++) {
#pragma unroll
        for (int off = 16; off; off >>= 1) {
            psum[j] += __shfl_down_sync(0xffffffffu, psum[j], off);
            psq[j]  += __shfl_down_sync(0xffffffffu, psq[j],  off);
        }
    }
    if ((tid & 31) == 0) {
        int gc = col0 + cg * 8;
#pragma unroll
        for (int j = 0; j < 8; j++) {
            atomicAdd(&sums[gc + j],        (double)psum[j]);
            atomicAdd(&sums[OUTF + gc + j], (double)psq[j]);
        }
    }
#pragma unroll
    for (int j = 0; j < 8; j++) {
#pragma unroll
        for (int off = 4; off; off >>= 1) {
            tmax[j] = fmaxf(tmax[j], __shfl_down_sync(0xffffffffu, tmax[j], off, 8));
            tmin[j] = fminf(tmin[j], __shfl_down_sync(0xffffffffu, tmin[j], off, 8));
        }
    }
    if ((rg & 7) == 0) {
        size_t samp = row0 / 32 + (rg >> 3);
        int gc = col0 + cg * 8;
        float* pma = &g_ymax[samp * 128 + gc];
        float* pmi = &g_ymin[samp * 128 + gc];
        ((float4*)pma)[0] = make_float4(tmax[0], tmax[1], tmax[2], tmax[3]);
        ((float4*)pma)[1] = make_float4(tmax[4], tmax[5], tmax[6], tmax[7]);
        ((float4*)pmi)[0] = make_float4(tmin[0], tmin[1], tmin[2], tmin[3]);
        ((float4*)pmi)[1] = make_float4(tmin[4], tmin[5], tmin[6], tmin[7]);
    }
}

__global__ void finalize_kernel(const float* __restrict__ g, const float* __restrict__ be,
                                int O, int soff, int scoff) {
    int c = threadIdx.x;
    if (c >= O) return;
    double n = (double)NROWS;
    double mean = g_sums[soff + c] / n;
    double var  = g_sums[soff + O + c] / n - mean * mean;
    double sc   = (double)g[c] * rsqrt(var + 1e-5);
    g_scale[scoff + c] = (float)sc;
    g_shift[scoff + c] = (float)((double)be[c] - mean * sc);
}

__global__ __launch_bounds__(128) void maxpool_kernel(float* __restrict__ out) {
    int bs = blockIdx.x, c = threadIdx.x;
    float sc = g_scale[128 + c], sh = g_shift[128 + c];
    float v = (sc >= 0.f) ? g_ymax[(size_t)bs * 128 + c] : g_ymin[(size_t)bs * 128 + c];
    out[OUT_OFF + (size_t)bs * 128 + c] = fmaxf(fmaf(v, sc, sh), 0.f);
}

// ============================ launcher ====================================
extern "C" void kernel_launch(void* const* d_in, const int* in_sizes, int n_in,
                              void* d_out, int out_size) {
    const float* data = (const float*)d_in[0];
    const float* feat = (const float*)d_in[1];
    const int*   initf = (const int*)d_in[2];
    const float* W0 = (const float*)d_in[3];  const float* b0 = (const float*)d_in[4];
    const float* g0 = (const float*)d_in[5];  const float* be0 = (const float*)d_in[6];
    const float* W1 = (const float*)d_in[7];  const float* b1 = (const float*)d_in[8];
    const float* g1 = (const float*)d_in[9];  const float* be1 = (const float*)d_in[10];
    const float* W2 = (const float*)d_in[11]; const float* b2 = (const float*)d_in[12];
    const float* g2 = (const float*)d_in[13]; const float* be2 = (const float*)d_in[14];
    float* out = (float*)d_out;

    const int smf = NPTS * 3 * 4 + 128 * 4;          // fps: 49664
    const int smb = 33824;                           // build (was 42048)
    const int sm0 = (68*132 + 68*64) * 4;            // 53312
    const int sm1 = (64*132 + 64*64) * 4;            // 50176
    const int sm2 = (64*132 + 64*64) * 4;            // 50176
    cudaFuncSetAttribute((const void*)fps_kernel,       cudaFuncAttributeMaxDynamicSharedMemorySize, smf);
    cudaFuncSetAttribute((const void*)build_kernel,     cudaFuncAttributeMaxDynamicSharedMemorySize, smb);
    cudaFuncSetAttribute((const void*)gemm01_kernel<0>, cudaFuncAttributeMaxDynamicSharedMemorySize, sm0);
    cudaFuncSetAttribute((const void*)gemm01_kernel<1>, cudaFuncAttributeMaxDynamicSharedMemorySize, sm1);
    cudaFuncSetAttribute((const void*)gemm2_kernel,     cudaFuncAttributeMaxDynamicSharedMemorySize, sm2);

    zero_stats_kernel<<<1, 512>>>();
    fps_kernel<<<NBATCH, 1024, smf>>>(data, initf, out);
    probe_kernel<<<1, 32>>>();   // keeps ncu capture window on build_kernel
    build_kernel<<<NBATCH * NSAMP, 512, smb>>>(data, feat);
    gemm01_kernel<0><<<NROWS / 128, 256, sm0>>>(W0, b0);
    finalize_kernel<<<1, 128>>>(g0, be0, 64, 0, 0);
    gemm01_kernel<1><<<NROWS / 128, 256, sm1>>>(W1, b1);
    finalize_kernel<<<1, 128>>>(g1, be1, 64, 128, 64);
    gemm2_kernel<<<dim3(NROWS / 128, 2), 256, sm2>>>(W2, b2);
    finalize_kernel<<<1, 128>>>(g2, be2, 128, 256, 128);
    maxpool_kernel<<<NBATCH * NSAMP, 128>>>(out);
}